// round 2
// baseline (speedup 1.0000x reference)
#include <cuda_runtime.h>
#include <math.h>

#define DIM   512
#define CDIM  14
#define KSIZE 16384

// scratch (no allocations allowed — device globals)
__device__ float g_p[8192 * CDIM];
__device__ float g_avg[KSIZE];
__device__ float g_scal[2];   // [0] = commit sum, [1] = per-sample entropy sum

// ---------------------------------------------------------------- K0: zero
__global__ void k0_zero() {
    int i = blockIdx.x * blockDim.x + threadIdx.x;
    for (int j = i; j < KSIZE; j += gridDim.x * blockDim.x) g_avg[j] = 0.f;
    if (i < 2) g_scal[i] = 0.f;
}

// ---------------------------------------------------------------- K1
// grid = ntok/32 blocks x 256 threads. Each warp handles 4 tokens.
// Computes p = x@w_in^T + b_in, indices, commit partial, p -> g_p,
// and out = sign(p)@w_out^T + b_out.
// w_in read from global (28KB, L1-resident after first token, float4 coalesced).
// w_out staged transposed in static shared (global layout would be stride-14).
__global__ __launch_bounds__(256) void k1(
    const float* __restrict__ x,
    const float* __restrict__ w_in,   // [14][512] row-major
    const float* __restrict__ b_in,   // [14]
    const float* __restrict__ w_out,  // [512][14] row-major
    const float* __restrict__ b_out,  // [512]
    float* __restrict__ out,
    float* __restrict__ idx_out)
{
    __shared__ float s_wout[CDIM * DIM];   // transposed [c*512+d]
    __shared__ float s_bout[DIM];
    __shared__ float s_bin[16];

    int tid = threadIdx.x;
    for (int i = tid; i < CDIM * DIM; i += 256) {
        int d = i / CDIM, c = i % CDIM;
        s_wout[c * DIM + d] = w_out[i];
    }
    for (int i = tid; i < DIM; i += 256) s_bout[i] = b_out[i];
    if (tid < CDIM) s_bin[tid] = b_in[tid];
    __syncthreads();

    int w = tid >> 5, l = tid & 31;
    const float4* win4  = (const float4*)w_in;
    const float4* wout4 = (const float4*)s_wout;
    const float4* bout4 = (const float4*)s_bout;

    float commit_acc = 0.f;

    #pragma unroll 1
    for (int t = 0; t < 4; t++) {
        int token = (blockIdx.x * 8 + w) * 4 + t;

        const float4* xp = (const float4*)(x + (size_t)token * DIM);
        float4 xv[4];
        #pragma unroll
        for (int k = 0; k < 4; k++) xv[k] = xp[k * 32 + l];

        float p[CDIM];
        #pragma unroll
        for (int c = 0; c < CDIM; c++) {
            float s = 0.f;
            #pragma unroll
            for (int k = 0; k < 4; k++) {
                float4 wv = win4[c * 128 + k * 32 + l];
                s += xv[k].x * wv.x + xv[k].y * wv.y + xv[k].z * wv.z + xv[k].w * wv.w;
            }
            #pragma unroll
            for (int off = 16; off; off >>= 1) s += __shfl_xor_sync(0xffffffffu, s, off);
            p[c] = s + s_bin[c];
        }

        unsigned idx = 0;
        float sgn[CDIM];
        #pragma unroll
        for (int c = 0; c < CDIM; c++) {
            bool pos = p[c] > 0.f;
            sgn[c] = pos ? 1.f : -1.f;
            idx |= (pos ? 1u : 0u) << (13 - c);
            float d = p[c] - sgn[c];
            commit_acc += d * d;
        }
        if (l == 0) {
            idx_out[token] = (float)idx;
            #pragma unroll
            for (int c = 0; c < CDIM; c++) g_p[token * CDIM + c] = p[c];
        }

        float4* op = (float4*)(out + (size_t)token * DIM);
        #pragma unroll
        for (int k = 0; k < 4; k++) {
            float4 acc = bout4[k * 32 + l];
            #pragma unroll
            for (int c = 0; c < CDIM; c++) {
                float4 wv = wout4[c * 128 + k * 32 + l];
                acc.x += sgn[c] * wv.x;
                acc.y += sgn[c] * wv.y;
                acc.z += sgn[c] * wv.z;
                acc.w += sgn[c] * wv.w;
            }
            op[k * 32 + l] = acc;
        }
    }
    if (l == 0) atomicAdd(&g_scal[0], commit_acc);
}

// ---------------------------------------------------------------- K2
// grid = ntok/64 blocks x 256 threads. Per token: factorized prob
// prob_j = A[j>>7] * B[j&127]; accumulate sum over tokens into
// register acc[64] per thread (thread t owns j in [t*64, t*64+64)).
// Also accumulates per-sample entropy = sum_c H(Bernoulli(q_c)).
__global__ __launch_bounds__(256) void k2() {
    __shared__ float sA[128];
    __shared__ float sB[128];
    __shared__ float sQ[16];

    int tid = threadIdx.x;
    float acc[64];
    #pragma unroll
    for (int i = 0; i < 64; i++) acc[i] = 0.f;
    float hloc = 0.f;

    int base = blockIdx.x * 64;
    #pragma unroll 1
    for (int tok = 0; tok < 64; tok++) {
        int token = base + tok;
        if (tid < CDIM) {
            float p = g_p[token * CDIM + tid];
            float q = 1.f / (1.f + expf(-400.f * p));   // softmax factor per dim
            sQ[tid] = q;
            float qm = 1.f - q;
            hloc += -(q  * logf(fmaxf(q,  1e-20f)) +
                      qm * logf(fmaxf(qm, 1e-20f)));
        }
        __syncthreads();
        if (tid < 128) {                         // A over bits 13..7 (c = 0..6)
            float v = 1.f;
            #pragma unroll
            for (int c = 0; c < 7; c++)
                v *= ((tid >> (6 - c)) & 1) ? sQ[c] : (1.f - sQ[c]);
            sA[tid] = v;
        } else {                                 // B over bits 6..0 (c = 7..13)
            int lo = tid - 128;
            float v = 1.f;
            #pragma unroll
            for (int c = 7; c < 14; c++)
                v *= ((lo >> (13 - c)) & 1) ? sQ[c] : (1.f - sQ[c]);
            sB[lo] = v;
        }
        __syncthreads();
        float a = sA[tid >> 1];                  // constant per thread
        const float* bb = &sB[(tid & 1) * 64];
        #pragma unroll
        for (int i = 0; i < 64; i++) acc[i] += a * bb[i];
        __syncthreads();
    }

    #pragma unroll
    for (int i = 0; i < 64; i++) atomicAdd(&g_avg[tid * 64 + i], acc[i]);

    if (tid < 32) {   // hloc nonzero only for tid<14 (all in warp 0)
        #pragma unroll
        for (int off = 16; off; off >>= 1) hloc += __shfl_xor_sync(0xffffffffu, hloc, off);
        if (tid == 0) atomicAdd(&g_scal[1], hloc);
    }
}

// ---------------------------------------------------------------- K3
__global__ __launch_bounds__(256) void k3(float* __restrict__ aux_out, float inv_ntok) {
    __shared__ float sred[8];
    int tid = threadIdx.x;
    float s = 0.f;
    for (int i = tid; i < KSIZE; i += 256) {
        float a = g_avg[i] * inv_ntok;
        s += -a * logf(fmaxf(a, 1e-20f));
    }
    #pragma unroll
    for (int off = 16; off; off >>= 1) s += __shfl_xor_sync(0xffffffffu, s, off);
    if ((tid & 31) == 0) sred[tid >> 5] = s;
    __syncthreads();
    if (tid == 0) {
        float Hc = 0.f;
        #pragma unroll
        for (int i = 0; i < 8; i++) Hc += sred[i];
        float Hs = g_scal[1] * inv_ntok;                  // per_sample_entropy mean
        float commit = g_scal[0] * inv_ntok * (1.f / (float)CDIM);
        float aux = 0.1f * (Hs - Hc) + 0.25f * commit;
        *aux_out = aux;
    }
}

// ----------------------------------------------------------------
extern "C" void kernel_launch(void* const* d_in, const int* in_sizes, int n_in,
                              void* d_out, int out_size) {
    const float* x     = (const float*)d_in[0];
    const float* w_in  = (const float*)d_in[1];
    const float* b_in  = (const float*)d_in[2];
    const float* w_out = (const float*)d_in[3];
    const float* b_out = (const float*)d_in[4];

    int ntok = in_sizes[0] / DIM;               // 8192
    float* out     = (float*)d_out;
    float* idx_out = out + (size_t)ntok * DIM;
    float* aux_out = idx_out + ntok;

    k0_zero<<<64, 256>>>();
    k1<<<ntok / 32, 256>>>(x, w_in, b_in, w_out, b_out, out, idx_out);
    k2<<<ntok / 64, 256>>>();
    k3<<<1, 256>>>(aux_out, 1.f / (float)ntok);
}

// round 3
// speedup vs baseline: 1.1512x; 1.1512x over previous
#include <cuda_runtime.h>
#include <math.h>

#define DIM   512
#define CDIM  14
#define KSIZE 16384

// scratch (no allocations allowed — device globals)
__device__ float g_p[8192 * CDIM];
__device__ float g_avg[KSIZE];
__device__ float g_scal[3];   // [0]=commit sum, [1]=per-sample entropy sum, [2]=codebook-entropy partial

// ---------------------------------------------------------------- K0: zero
__global__ void k0_zero() {
    int i = blockIdx.x * blockDim.x + threadIdx.x;
    for (int j = i; j < KSIZE; j += gridDim.x * blockDim.x) g_avg[j] = 0.f;
    if (i < 3) g_scal[i] = 0.f;
}

// ---------------------------------------------------------------- K1
// grid = ntok/32 blocks x 256 threads. Each warp handles 4 tokens.
// p = x@w_in^T + b_in -> indices, commit partial, p -> g_p,
// out = sign(p)@w_out^T + b_out.
__global__ __launch_bounds__(256) void k1(
    const float* __restrict__ x,
    const float* __restrict__ w_in,   // [14][512]
    const float* __restrict__ b_in,   // [14]
    const float* __restrict__ w_out,  // [512][14]
    const float* __restrict__ b_out,  // [512]
    float* __restrict__ out,
    float* __restrict__ idx_out)
{
    __shared__ float s_wout[CDIM * DIM];   // transposed [c*512+d]
    __shared__ float s_bout[DIM];
    __shared__ float s_bin[16];

    int tid = threadIdx.x;
    for (int i = tid; i < CDIM * DIM; i += 256) {
        int d = i / CDIM, c = i % CDIM;
        s_wout[c * DIM + d] = w_out[i];
    }
    for (int i = tid; i < DIM; i += 256) s_bout[i] = b_out[i];
    if (tid < CDIM) s_bin[tid] = b_in[tid];
    __syncthreads();

    int w = tid >> 5, l = tid & 31;
    const float4* win4  = (const float4*)w_in;
    const float4* wout4 = (const float4*)s_wout;
    const float4* bout4 = (const float4*)s_bout;

    float commit_acc = 0.f;

    #pragma unroll 1
    for (int t = 0; t < 4; t++) {
        int token = (blockIdx.x * 8 + w) * 4 + t;

        const float4* xp = (const float4*)(x + (size_t)token * DIM);
        float4 xv[4];
        #pragma unroll
        for (int k = 0; k < 4; k++) xv[k] = xp[k * 32 + l];

        float p[CDIM];
        #pragma unroll
        for (int c = 0; c < CDIM; c++) {
            float s = 0.f;
            #pragma unroll
            for (int k = 0; k < 4; k++) {
                float4 wv = win4[c * 128 + k * 32 + l];
                s += xv[k].x * wv.x + xv[k].y * wv.y + xv[k].z * wv.z + xv[k].w * wv.w;
            }
            #pragma unroll
            for (int off = 16; off; off >>= 1) s += __shfl_xor_sync(0xffffffffu, s, off);
            p[c] = s + s_bin[c];
        }

        unsigned idx = 0;
        float sgn[CDIM];
        #pragma unroll
        for (int c = 0; c < CDIM; c++) {
            bool pos = p[c] > 0.f;
            sgn[c] = pos ? 1.f : -1.f;
            idx |= (pos ? 1u : 0u) << (13 - c);
            float d = p[c] - sgn[c];
            commit_acc += d * d;
        }
        if (l == 0) {
            idx_out[token] = (float)idx;
            #pragma unroll
            for (int c = 0; c < CDIM; c++) g_p[token * CDIM + c] = p[c];
        }

        float4* op = (float4*)(out + (size_t)token * DIM);
        #pragma unroll
        for (int k = 0; k < 4; k++) {
            float4 acc = bout4[k * 32 + l];
            #pragma unroll
            for (int c = 0; c < CDIM; c++) {
                float4 wv = wout4[c * 128 + k * 32 + l];
                acc.x += sgn[c] * wv.x;
                acc.y += sgn[c] * wv.y;
                acc.z += sgn[c] * wv.z;
                acc.w += sgn[c] * wv.w;
            }
            op[k * 32 + l] = acc;
        }
    }
    if (l == 0) atomicAdd(&g_scal[0], commit_acc);
}

// ---------------------------------------------------------------- K2
// grid = ntok/32 blocks x 256 threads, 32 tokens per block.
// Stage 1: coalesced load of all 32x14 p values, sigmoid, per-sample entropy.
// Stage 2: per 2 tokens: build A[128]/B[128] factor tables, accumulate
//          outer product A[j>>7]*B[j&127] into register acc[64] (thread t
//          owns j in [t*64, t*64+64)) with float4 shared loads.
#define T2 32
__global__ __launch_bounds__(256) void k2() {
    __shared__ float sQ[T2 * 16];                  // [tok*16 + c]
    __shared__ __align__(16) float sA[2][128];
    __shared__ __align__(16) float sB[2][128];

    int tid = threadIdx.x;
    int base = blockIdx.x * T2;

    // ---- stage 1: coalesced p load + sigmoid + per-sample entropy
    float hloc = 0.f;
    for (int i = tid; i < T2 * CDIM; i += 256) {
        int tok = i / CDIM, c = i % CDIM;
        float p = g_p[(size_t)base * CDIM + i];
        float q = 1.f / (1.f + expf(-400.f * p));
        sQ[tok * 16 + c] = q;
        float qm = 1.f - q;
        hloc += -(q  * logf(fmaxf(q,  1e-20f)) +
                  qm * logf(fmaxf(qm, 1e-20f)));
    }
    #pragma unroll
    for (int off = 16; off; off >>= 1) hloc += __shfl_xor_sync(0xffffffffu, hloc, off);
    if ((tid & 31) == 0 && hloc != 0.f) atomicAdd(&g_scal[1], hloc);
    __syncthreads();

    // ---- stage 2
    float acc[64];
    #pragma unroll
    for (int i = 0; i < 64; i++) acc[i] = 0.f;

    int hi = tid >> 1;                 // A index for this thread
    int lob = (tid & 1) * 64;          // B sub-block base

    #pragma unroll 1
    for (int t = 0; t < T2; t += 2) {
        // build tables for tokens t and t+1
        #pragma unroll
        for (int u = 0; u < 2; u++) {
            const float* q = &sQ[(t + u) * 16];
            if (tid < 128) {                       // A over c = 0..6 (bits 13..7)
                float v = 1.f;
                #pragma unroll
                for (int c = 0; c < 7; c++)
                    v *= ((tid >> (6 - c)) & 1) ? q[c] : (1.f - q[c]);
                sA[u][tid] = v;
            } else {                               // B over c = 7..13 (bits 6..0)
                int lo = tid - 128;
                float v = 1.f;
                #pragma unroll
                for (int c = 7; c < 14; c++)
                    v *= ((lo >> (13 - c)) & 1) ? q[c] : (1.f - q[c]);
                sB[u][lo] = v;
            }
        }
        __syncthreads();
        #pragma unroll
        for (int u = 0; u < 2; u++) {
            float a = sA[u][hi];
            const float4* b4 = (const float4*)&sB[u][lob];
            #pragma unroll
            for (int i = 0; i < 16; i++) {
                float4 bv = b4[i];
                acc[4*i+0] += a * bv.x;
                acc[4*i+1] += a * bv.y;
                acc[4*i+2] += a * bv.z;
                acc[4*i+3] += a * bv.w;
            }
        }
        __syncthreads();
    }

    #pragma unroll
    for (int i = 0; i < 64; i++) atomicAdd(&g_avg[tid * 64 + i], acc[i]);
}

// ---------------------------------------------------------------- K3a: codebook entropy partial (parallel)
__global__ __launch_bounds__(256) void k3a(float inv_ntok) {
    int gid = blockIdx.x * 256 + threadIdx.x;
    float s = 0.f;
    for (int i = gid; i < KSIZE; i += gridDim.x * 256) {
        float a = g_avg[i] * inv_ntok;
        s += -a * logf(fmaxf(a, 1e-20f));
    }
    #pragma unroll
    for (int off = 16; off; off >>= 1) s += __shfl_xor_sync(0xffffffffu, s, off);
    if ((threadIdx.x & 31) == 0) atomicAdd(&g_scal[2], s);
}

// ---------------------------------------------------------------- K3b: final scalar
__global__ void k3b(float* __restrict__ aux_out, float inv_ntok) {
    if (threadIdx.x == 0) {
        float Hc = g_scal[2];
        float Hs = g_scal[1] * inv_ntok;
        float commit = g_scal[0] * inv_ntok * (1.f / (float)CDIM);
        *aux_out = 0.1f * (Hs - Hc) + 0.25f * commit;
    }
}

// ----------------------------------------------------------------
extern "C" void kernel_launch(void* const* d_in, const int* in_sizes, int n_in,
                              void* d_out, int out_size) {
    const float* x     = (const float*)d_in[0];
    const float* w_in  = (const float*)d_in[1];
    const float* b_in  = (const float*)d_in[2];
    const float* w_out = (const float*)d_in[3];
    const float* b_out = (const float*)d_in[4];

    int ntok = in_sizes[0] / DIM;               // 8192
    float* out     = (float*)d_out;
    float* idx_out = out + (size_t)ntok * DIM;
    float* aux_out = idx_out + ntok;

    float inv_ntok = 1.f / (float)ntok;

    k0_zero<<<64, 256>>>();
    k1<<<ntok / 32, 256>>>(x, w_in, b_in, w_out, b_out, out, idx_out);
    k2<<<ntok / T2, 256>>>();
    k3a<<<32, 256>>>(inv_ntok);
    k3b<<<1, 32>>>(aux_out, inv_ntok);
}

// round 4
// speedup vs baseline: 1.8154x; 1.5770x over previous
#include <cuda_runtime.h>
#include <math.h>

#define DIM   512
#define CDIM  14
#define KSIZE 16384
#define NBLK  256      // 8192 tokens / 32 per block

// scratch — static device globals (no allocation allowed)
__device__ float g_part[NBLK * KSIZE];   // per-block partial prob sums (16MB)
__device__ float g_sc[NBLK];             // per-block commit partial
__device__ float g_se[NBLK];             // per-block sample-entropy partial
__device__ float g_hc[64];               // per-block codebook-entropy partial

// ---------------------------------------------------------------- fused kernel
// grid = 256 blocks x 256 threads; block owns 32 tokens.
// Stage A: p = x@w_in^T + b_in (per-warp, shuffle reduce), indices, commit,
//          out = sign(p)@w_out^T + b_out, p -> smem.
// Stage B: q = sigmoid(400p), per-sample entropy partial.
// Stage C: per 2 tokens build A[128]/B[128] factor tables, accumulate rank-1
//          outer products into acc[64] (code j = w*2048 + i*128 + l*4 + k).
// Epilogue: coalesced STG.128 partials, block-reduced scalars. No atomics.
__global__ __launch_bounds__(256, 2) void kF(
    const float* __restrict__ x,
    const float* __restrict__ w_in,   // [14][512]
    const float* __restrict__ b_in,   // [14]
    const float* __restrict__ w_out,  // [512][14]
    const float* __restrict__ b_out,  // [512]
    float* __restrict__ out,
    float* __restrict__ idx_out)
{
    __shared__ float s_wout[CDIM * DIM];   // transposed [c*512+d]
    __shared__ float s_bout[DIM];
    __shared__ float s_bin[16];
    __shared__ float sP[32 * 16];          // p values [tok*16+c]
    __shared__ float sQ[32 * 16];          // sigmoid values
    __shared__ __align__(16) float sA[2][128];
    __shared__ __align__(16) float sB[2][128];
    __shared__ float sred[16];

    int tid = threadIdx.x;
    for (int i = tid; i < CDIM * DIM; i += 256) {
        int d = i / CDIM, c = i % CDIM;
        s_wout[c * DIM + d] = w_out[i];
    }
    for (int i = tid; i < DIM; i += 256) s_bout[i] = b_out[i];
    if (tid < CDIM) s_bin[tid] = b_in[tid];
    __syncthreads();

    int w = tid >> 5, l = tid & 31;
    const float4* win4  = (const float4*)w_in;
    const float4* wout4 = (const float4*)s_wout;
    const float4* bout4 = (const float4*)s_bout;

    float commit_acc = 0.f;

    // ---- stage A: projection / quantize / project-out (warp per token x4)
    #pragma unroll 1
    for (int t = 0; t < 4; t++) {
        int tok   = w * 4 + t;
        int token = blockIdx.x * 32 + tok;

        const float4* xp = (const float4*)(x + (size_t)token * DIM);
        float4 xv[4];
        #pragma unroll
        for (int k = 0; k < 4; k++) xv[k] = xp[k * 32 + l];

        float p[CDIM];
        #pragma unroll
        for (int c = 0; c < CDIM; c++) {
            float s = 0.f;
            #pragma unroll
            for (int k = 0; k < 4; k++) {
                float4 wv = win4[c * 128 + k * 32 + l];
                s += xv[k].x * wv.x + xv[k].y * wv.y + xv[k].z * wv.z + xv[k].w * wv.w;
            }
            #pragma unroll
            for (int off = 16; off; off >>= 1) s += __shfl_xor_sync(0xffffffffu, s, off);
            p[c] = s + s_bin[c];
        }

        unsigned idx = 0;
        float sgn[CDIM];
        #pragma unroll
        for (int c = 0; c < CDIM; c++) {
            bool pos = p[c] > 0.f;
            sgn[c] = pos ? 1.f : -1.f;
            idx |= (pos ? 1u : 0u) << (13 - c);
            float d = p[c] - sgn[c];
            commit_acc += d * d;           // same in every lane; lane 0 used
        }
        if (l == 0) {
            idx_out[token] = (float)idx;
            #pragma unroll
            for (int c = 0; c < CDIM; c++) sP[tok * 16 + c] = p[c];
        }

        float4* op = (float4*)(out + (size_t)token * DIM);
        #pragma unroll
        for (int k = 0; k < 4; k++) {
            float4 acc4 = bout4[k * 32 + l];
            #pragma unroll
            for (int c = 0; c < CDIM; c++) {
                float4 wv = wout4[c * 128 + k * 32 + l];
                acc4.x += sgn[c] * wv.x;
                acc4.y += sgn[c] * wv.y;
                acc4.z += sgn[c] * wv.z;
                acc4.w += sgn[c] * wv.w;
            }
            op[k * 32 + l] = acc4;
        }
    }
    __syncthreads();

    // ---- stage B: sigmoids + per-sample entropy
    float hloc = 0.f;
    for (int i = tid; i < 32 * CDIM; i += 256) {
        int tok = i / CDIM, c = i % CDIM;
        float p = sP[tok * 16 + c];
        float q = 1.f / (1.f + expf(-400.f * p));
        sQ[tok * 16 + c] = q;
        float qm = 1.f - q;
        hloc += -(q  * logf(fmaxf(q,  1e-20f)) +
                  qm * logf(fmaxf(qm, 1e-20f)));
    }
    __syncthreads();

    // ---- stage C: factorized outer-product accumulation
    float acc[64];
    #pragma unroll
    for (int i = 0; i < 64; i++) acc[i] = 0.f;

    #pragma unroll 1
    for (int t = 0; t < 32; t += 2) {
        #pragma unroll
        for (int u = 0; u < 2; u++) {
            const float* q = &sQ[(t + u) * 16];
            if (tid < 128) {                       // A over c = 0..6 (bits 13..7)
                float v = 1.f;
                #pragma unroll
                for (int c = 0; c < 7; c++)
                    v *= ((tid >> (6 - c)) & 1) ? q[c] : (1.f - q[c]);
                sA[u][tid] = v;
            } else {                               // B over c = 7..13 (bits 6..0)
                int lo = tid - 128;
                float v = 1.f;
                #pragma unroll
                for (int c = 7; c < 14; c++)
                    v *= ((lo >> (13 - c)) & 1) ? q[c] : (1.f - q[c]);
                sB[u][lo] = v;
            }
        }
        __syncthreads();
        #pragma unroll
        for (int u = 0; u < 2; u++) {
            float4 bv = ((const float4*)sB[u])[l];     // sB[l*4 .. l*4+3]
            #pragma unroll
            for (int i = 0; i < 16; i++) {
                float a = sA[u][w * 16 + i];           // broadcast
                acc[4*i+0] += a * bv.x;
                acc[4*i+1] += a * bv.y;
                acc[4*i+2] += a * bv.z;
                acc[4*i+3] += a * bv.w;
            }
        }
        __syncthreads();
    }

    // ---- epilogue: coalesced partial writes (code j = w*2048 + i*128 + l*4 + k)
    float4* dst = (float4*)(g_part + (size_t)blockIdx.x * KSIZE + w * 2048);
    #pragma unroll
    for (int i = 0; i < 16; i++)
        dst[i * 32 + l] = make_float4(acc[4*i], acc[4*i+1], acc[4*i+2], acc[4*i+3]);

    // ---- block scalar reductions
    #pragma unroll
    for (int off = 16; off; off >>= 1) hloc += __shfl_xor_sync(0xffffffffu, hloc, off);
    if (l == 0) { sred[w] = commit_acc; sred[8 + w] = hloc; }
    __syncthreads();
    if (tid == 0) {
        float c = 0.f, h = 0.f;
        #pragma unroll
        for (int i = 0; i < 8; i++) { c += sred[i]; h += sred[8 + i]; }
        g_sc[blockIdx.x] = c;
        g_se[blockIdx.x] = h;
    }
}

// ---------------------------------------------------------------- K3a: reduce partials -> codebook entropy partials
__global__ __launch_bounds__(256) void k3a(float inv_ntok) {
    int gid = blockIdx.x * 256 + threadIdx.x;     // code index, grid=64
    const float* p = g_part + gid;
    float a0 = 0.f, a1 = 0.f, a2 = 0.f, a3 = 0.f;
    #pragma unroll 4
    for (int b = 0; b < NBLK; b += 4) {
        a0 += p[(size_t)(b    ) * KSIZE];
        a1 += p[(size_t)(b + 1) * KSIZE];
        a2 += p[(size_t)(b + 2) * KSIZE];
        a3 += p[(size_t)(b + 3) * KSIZE];
    }
    float a = ((a0 + a1) + (a2 + a3)) * inv_ntok;
    float s = -a * logf(fmaxf(a, 1e-20f));

    __shared__ float sred[8];
    #pragma unroll
    for (int off = 16; off; off >>= 1) s += __shfl_xor_sync(0xffffffffu, s, off);
    if ((threadIdx.x & 31) == 0) sred[threadIdx.x >> 5] = s;
    __syncthreads();
    if (threadIdx.x == 0) {
        float t = 0.f;
        #pragma unroll
        for (int i = 0; i < 8; i++) t += sred[i];
        g_hc[blockIdx.x] = t;
    }
}

// ---------------------------------------------------------------- K3b: final scalar
__global__ __launch_bounds__(256) void k3b(float* __restrict__ aux_out, float inv_ntok) {
    int tid = threadIdx.x;
    float hc = (tid < 64) ? g_hc[tid] : 0.f;
    float sc = g_sc[tid];
    float se = g_se[tid];
    #pragma unroll
    for (int off = 16; off; off >>= 1) {
        hc += __shfl_xor_sync(0xffffffffu, hc, off);
        sc += __shfl_xor_sync(0xffffffffu, sc, off);
        se += __shfl_xor_sync(0xffffffffu, se, off);
    }
    __shared__ float sr[3][8];
    int w = tid >> 5;
    if ((tid & 31) == 0) { sr[0][w] = hc; sr[1][w] = sc; sr[2][w] = se; }
    __syncthreads();
    if (tid == 0) {
        float Hc = 0.f, C = 0.f, Hs = 0.f;
        #pragma unroll
        for (int i = 0; i < 8; i++) { Hc += sr[0][i]; C += sr[1][i]; Hs += sr[2][i]; }
        float per_sample = Hs * inv_ntok;
        float commit = C * inv_ntok * (1.f / (float)CDIM);
        *aux_out = 0.1f * (per_sample - Hc) + 0.25f * commit;
    }
}

// ----------------------------------------------------------------
extern "C" void kernel_launch(void* const* d_in, const int* in_sizes, int n_in,
                              void* d_out, int out_size) {
    const float* x     = (const float*)d_in[0];
    const float* w_in  = (const float*)d_in[1];
    const float* b_in  = (const float*)d_in[2];
    const float* w_out = (const float*)d_in[3];
    const float* b_out = (const float*)d_in[4];

    int ntok = in_sizes[0] / DIM;               // 8192
    float* out     = (float*)d_out;
    float* idx_out = out + (size_t)ntok * DIM;
    float* aux_out = idx_out + ntok;

    float inv_ntok = 1.f / (float)ntok;

    kF<<<ntok / 32, 256>>>(x, w_in, b_in, w_out, b_out, out, idx_out);
    k3a<<<64, 256>>>(inv_ntok);
    k3b<<<1, 256>>>(aux_out, inv_ntok);
}

// round 5
// speedup vs baseline: 2.6773x; 1.4748x over previous
#include <cuda_runtime.h>
#include <math.h>

#define DIM   512
#define CDIM  14
#define KSIZE 16384
#define NBLK  256      // 8192 tokens / 32 per block

// scratch — static device globals (no allocation allowed)
__device__ float g_part[NBLK * KSIZE];   // per-block partial prob sums (16MB)
__device__ float g_sc[NBLK];             // per-block commit partial
__device__ float g_se[NBLK];             // per-block sample-entropy partial
__device__ float g_hc[64];               // per-block codebook-entropy partial

// ---------------------------------------------------------------- fused kernel
// grid = 256 blocks x 256 threads; block owns 32 tokens (4 per warp).
// Stage A: 2 tokens jointly per pass — one w_in/w_out vector load feeds both.
// Stage B: q = sigmoid(400p), per-sample entropy partial.
// Stage C: 4 tokens per barrier phase; A table loaded to registers via
//          4x broadcast LDS.128; 64-FFMA register block per token.
__global__ __launch_bounds__(256, 2) void kF(
    const float* __restrict__ x,
    const float* __restrict__ w_in,   // [14][512]
    const float* __restrict__ b_in,   // [14]
    const float* __restrict__ w_out,  // [512][14]
    const float* __restrict__ b_out,  // [512]
    float* __restrict__ out,
    float* __restrict__ idx_out)
{
    __shared__ float s_wout[CDIM * DIM];   // transposed [c*512+d]
    __shared__ float s_bout[DIM];
    __shared__ float s_bin[16];
    __shared__ float sQ[32 * 16];          // sigmoid values [tok*16+c]
    __shared__ float sP[32 * 16];          // p values
    __shared__ __align__(16) float sA[4][128];
    __shared__ __align__(16) float sB[4][128];
    __shared__ float sred[16];

    int tid = threadIdx.x;
    for (int i = tid; i < CDIM * DIM; i += 256) {
        int d = i / CDIM, c = i % CDIM;
        s_wout[c * DIM + d] = w_out[i];
    }
    for (int i = tid; i < DIM; i += 256) s_bout[i] = b_out[i];
    if (tid < CDIM) s_bin[tid] = b_in[tid];
    __syncthreads();

    int w = tid >> 5, l = tid & 31;
    const float4* win4  = (const float4*)w_in;
    const float4* wout4 = (const float4*)s_wout;
    const float4* bout4 = (const float4*)s_bout;

    float commit_acc = 0.f;

    // ---- stage A: 2 tokens per pass, shared weight loads
    #pragma unroll 1
    for (int pair = 0; pair < 2; pair++) {
        int tok0   = w * 4 + pair * 2;
        int token0 = blockIdx.x * 32 + tok0;

        const float4* xp0 = (const float4*)(x + (size_t)token0 * DIM);
        const float4* xp1 = (const float4*)(x + (size_t)(token0 + 1) * DIM);
        float4 xv0[4], xv1[4];
        #pragma unroll
        for (int k = 0; k < 4; k++) { xv0[k] = xp0[k * 32 + l]; xv1[k] = xp1[k * 32 + l]; }

        float p0[CDIM], p1[CDIM];
        #pragma unroll
        for (int c = 0; c < CDIM; c++) {
            float s0 = 0.f, s1 = 0.f;
            #pragma unroll
            for (int k = 0; k < 4; k++) {
                float4 wv = win4[c * 128 + k * 32 + l];
                s0 += xv0[k].x * wv.x + xv0[k].y * wv.y + xv0[k].z * wv.z + xv0[k].w * wv.w;
                s1 += xv1[k].x * wv.x + xv1[k].y * wv.y + xv1[k].z * wv.z + xv1[k].w * wv.w;
            }
            #pragma unroll
            for (int off = 16; off; off >>= 1) {
                s0 += __shfl_xor_sync(0xffffffffu, s0, off);
                s1 += __shfl_xor_sync(0xffffffffu, s1, off);
            }
            p0[c] = s0 + s_bin[c];
            p1[c] = s1 + s_bin[c];
        }

        unsigned idx0 = 0, idx1 = 0;
        #pragma unroll
        for (int c = 0; c < CDIM; c++) {
            bool q0 = p0[c] > 0.f, q1 = p1[c] > 0.f;
            idx0 |= (q0 ? 1u : 0u) << (13 - c);
            idx1 |= (q1 ? 1u : 0u) << (13 - c);
            float sg0 = q0 ? 1.f : -1.f, sg1 = q1 ? 1.f : -1.f;
            float d0 = p0[c] - sg0, d1 = p1[c] - sg1;
            commit_acc += d0 * d0 + d1 * d1;     // identical in all lanes
        }
        if (l == 0) {
            idx_out[token0]     = (float)idx0;
            idx_out[token0 + 1] = (float)idx1;
            #pragma unroll
            for (int c = 0; c < CDIM; c++) {
                sP[tok0 * 16 + c]       = p0[c];
                sP[(tok0 + 1) * 16 + c] = p1[c];
            }
        }
        // reuse p arrays as signs
        #pragma unroll
        for (int c = 0; c < CDIM; c++) {
            p0[c] = (p0[c] > 0.f) ? 1.f : -1.f;
            p1[c] = (p1[c] > 0.f) ? 1.f : -1.f;
        }

        float4* op0 = (float4*)(out + (size_t)token0 * DIM);
        float4* op1 = (float4*)(out + (size_t)(token0 + 1) * DIM);
        #pragma unroll
        for (int k = 0; k < 4; k++) {
            float4 a0 = bout4[k * 32 + l];
            float4 a1 = a0;
            #pragma unroll
            for (int c = 0; c < CDIM; c++) {
                float4 wv = wout4[c * 128 + k * 32 + l];
                a0.x += p0[c] * wv.x; a0.y += p0[c] * wv.y;
                a0.z += p0[c] * wv.z; a0.w += p0[c] * wv.w;
                a1.x += p1[c] * wv.x; a1.y += p1[c] * wv.y;
                a1.z += p1[c] * wv.z; a1.w += p1[c] * wv.w;
            }
            op0[k * 32 + l] = a0;
            op1[k * 32 + l] = a1;
        }
    }
    __syncthreads();

    // ---- stage B: sigmoids + per-sample entropy partial
    float hloc = 0.f;
    for (int i = tid; i < 32 * CDIM; i += 256) {
        int tok = i / CDIM, c = i % CDIM;
        float p = sP[tok * 16 + c];
        float q = 1.f / (1.f + __expf(-400.f * p));
        sQ[tok * 16 + c] = q;
        float qm = 1.f - q;
        hloc += -(q  * __logf(fmaxf(q,  1e-20f)) +
                  qm * __logf(fmaxf(qm, 1e-20f)));
    }
    __syncthreads();

    // ---- stage C: factorized outer-product accumulation, 4 tokens/phase
    float acc[64];
    #pragma unroll
    for (int i = 0; i < 64; i++) acc[i] = 0.f;

    #pragma unroll 1
    for (int t = 0; t < 32; t += 4) {
        #pragma unroll
        for (int u = 0; u < 4; u++) {
            const float* q = &sQ[(t + u) * 16];
            if (tid < 128) {                       // A over c = 0..6 (bits 13..7)
                float v = 1.f;
                #pragma unroll
                for (int c = 0; c < 7; c++)
                    v *= ((tid >> (6 - c)) & 1) ? q[c] : (1.f - q[c]);
                sA[u][tid] = v;
            } else {                               // B over c = 7..13 (bits 6..0)
                int lo = tid - 128;
                float v = 1.f;
                #pragma unroll
                for (int c = 7; c < 14; c++)
                    v *= ((lo >> (13 - c)) & 1) ? q[c] : (1.f - q[c]);
                sB[u][lo] = v;
            }
        }
        __syncthreads();
        #pragma unroll
        for (int u = 0; u < 4; u++) {
            float4 bv = ((const float4*)sB[u])[l];           // lane-varying
            const float4* ap = (const float4*)&sA[u][w * 16]; // warp-broadcast
            float4 aa[4];
            aa[0] = ap[0]; aa[1] = ap[1]; aa[2] = ap[2]; aa[3] = ap[3];
            const float* av = (const float*)aa;
            #pragma unroll
            for (int i = 0; i < 16; i++) {
                float a = av[i];
                acc[4*i+0] += a * bv.x;
                acc[4*i+1] += a * bv.y;
                acc[4*i+2] += a * bv.z;
                acc[4*i+3] += a * bv.w;
            }
        }
        __syncthreads();
    }

    // ---- epilogue: coalesced partial writes (code j = w*2048 + i*128 + l*4 + k)
    float4* dst = (float4*)(g_part + (size_t)blockIdx.x * KSIZE + w * 2048);
    #pragma unroll
    for (int i = 0; i < 16; i++)
        dst[i * 32 + l] = make_float4(acc[4*i], acc[4*i+1], acc[4*i+2], acc[4*i+3]);

    // ---- block scalar reductions
    #pragma unroll
    for (int off = 16; off; off >>= 1) hloc += __shfl_xor_sync(0xffffffffu, hloc, off);
    if (l == 0) { sred[w] = commit_acc; sred[8 + w] = hloc; }
    __syncthreads();
    if (tid == 0) {
        float c = 0.f, h = 0.f;
        #pragma unroll
        for (int i = 0; i < 8; i++) { c += sred[i]; h += sred[8 + i]; }
        g_sc[blockIdx.x] = c;
        g_se[blockIdx.x] = h;
    }
}

// ---------------------------------------------------------------- K3a: reduce partials -> codebook entropy partials
__global__ __launch_bounds__(256) void k3a(float inv_ntok) {
    int gid = blockIdx.x * 256 + threadIdx.x;     // code index, grid=64
    const float* p = g_part + gid;
    float a0 = 0.f, a1 = 0.f, a2 = 0.f, a3 = 0.f;
    #pragma unroll 4
    for (int b = 0; b < NBLK; b += 4) {
        a0 += p[(size_t)(b    ) * KSIZE];
        a1 += p[(size_t)(b + 1) * KSIZE];
        a2 += p[(size_t)(b + 2) * KSIZE];
        a3 += p[(size_t)(b + 3) * KSIZE];
    }
    float a = ((a0 + a1) + (a2 + a3)) * inv_ntok;
    float s = -a * __logf(fmaxf(a, 1e-20f));

    __shared__ float sred[8];
    #pragma unroll
    for (int off = 16; off; off >>= 1) s += __shfl_xor_sync(0xffffffffu, s, off);
    if ((threadIdx.x & 31) == 0) sred[threadIdx.x >> 5] = s;
    __syncthreads();
    if (threadIdx.x == 0) {
        float t = 0.f;
        #pragma unroll
        for (int i = 0; i < 8; i++) t += sred[i];
        g_hc[blockIdx.x] = t;
    }
}

// ---------------------------------------------------------------- K3b: final scalar
__global__ __launch_bounds__(256) void k3b(float* __restrict__ aux_out, float inv_ntok) {
    int tid = threadIdx.x;
    float hc = (tid < 64) ? g_hc[tid] : 0.f;
    float sc = g_sc[tid];
    float se = g_se[tid];
    #pragma unroll
    for (int off = 16; off; off >>= 1) {
        hc += __shfl_xor_sync(0xffffffffu, hc, off);
        sc += __shfl_xor_sync(0xffffffffu, sc, off);
        se += __shfl_xor_sync(0xffffffffu, se, off);
    }
    __shared__ float sr[3][8];
    int w = tid >> 5;
    if ((tid & 31) == 0) { sr[0][w] = hc; sr[1][w] = sc; sr[2][w] = se; }
    __syncthreads();
    if (tid == 0) {
        float Hc = 0.f, C = 0.f, Hs = 0.f;
        #pragma unroll
        for (int i = 0; i < 8; i++) { Hc += sr[0][i]; C += sr[1][i]; Hs += sr[2][i]; }
        float per_sample = Hs * inv_ntok;
        float commit = C * inv_ntok * (1.f / (float)CDIM);
        *aux_out = 0.1f * (per_sample - Hc) + 0.25f * commit;
    }
}

// ----------------------------------------------------------------
extern "C" void kernel_launch(void* const* d_in, const int* in_sizes, int n_in,
                              void* d_out, int out_size) {
    const float* x     = (const float*)d_in[0];
    const float* w_in  = (const float*)d_in[1];
    const float* b_in  = (const float*)d_in[2];
    const float* w_out = (const float*)d_in[3];
    const float* b_out = (const float*)d_in[4];

    int ntok = in_sizes[0] / DIM;               // 8192
    float* out     = (float*)d_out;
    float* idx_out = out + (size_t)ntok * DIM;
    float* aux_out = idx_out + ntok;

    float inv_ntok = 1.f / (float)ntok;

    kF<<<ntok / 32, 256>>>(x, w_in, b_in, w_out, b_out, out, idx_out);
    k3a<<<64, 256>>>(inv_ntok);
    k3b<<<1, 256>>>(aux_out, inv_ntok);
}

// round 6
// speedup vs baseline: 2.8507x; 1.0648x over previous
#include <cuda_runtime.h>
#include <math.h>

#define DIM   512
#define CDIM  14
#define KSIZE 16384
#define NBLK  256      // 8192 tokens / 32 per block

// scratch — static device globals (no allocation allowed)
__device__ float g_part[NBLK * KSIZE];   // per-block partial prob sums (16MB)
__device__ float g_sc[NBLK];             // per-block commit partial
__device__ float g_se[NBLK];             // per-block sample-entropy partial
__device__ float g_hc[64];               // per-block codebook-entropy partial

// ---------------------------------------------------------------- fused kernel
// grid = 256 blocks x 256 threads; block owns 32 tokens (4 per warp).
// Stage A: k-outer 4-token joint processing — every w_in / w_out vector load
//          is shared by 4 tokens (halves weight wavefronts vs 2-token).
// Stage B: q = sigmoid(400p), per-sample entropy partial.
// Stage C: 4 tokens per barrier phase; A table in registers via broadcast
//          LDS.128; 64-FFMA register block per token.
__global__ __launch_bounds__(256, 2) void kF(
    const float* __restrict__ x,
    const float* __restrict__ w_in,   // [14][512]
    const float* __restrict__ b_in,   // [14]
    const float* __restrict__ w_out,  // [512][14]
    const float* __restrict__ b_out,  // [512]
    float* __restrict__ out,
    float* __restrict__ idx_out)
{
    __shared__ float s_wout[CDIM * DIM];   // transposed [c*512+d]
    __shared__ float s_bout[DIM];
    __shared__ float s_bin[16];
    __shared__ float sQ[32 * 16];          // sigmoid values [tok*16+c]
    __shared__ float sP[32 * 16];          // p values
    __shared__ __align__(16) float sA[4][128];
    __shared__ __align__(16) float sB[4][128];
    __shared__ float sred[16];

    int tid = threadIdx.x;
    for (int i = tid; i < CDIM * DIM; i += 256) {
        int d = i / CDIM, c = i % CDIM;
        s_wout[c * DIM + d] = w_out[i];
    }
    for (int i = tid; i < DIM; i += 256) s_bout[i] = b_out[i];
    if (tid < CDIM) s_bin[tid] = b_in[tid];
    __syncthreads();

    int w = tid >> 5, l = tid & 31;
    const float4* win4  = (const float4*)w_in;
    const float4* wout4 = (const float4*)s_wout;
    const float4* bout4 = (const float4*)s_bout;

    int tok0   = w * 4;                     // first of this warp's 4 tokens
    int token0 = blockIdx.x * 32 + tok0;

    // ---- stage A part 1: projection, 4 tokens jointly, k-outer
    float s[4][CDIM];
    #pragma unroll
    for (int t = 0; t < 4; t++)
        #pragma unroll
        for (int c = 0; c < CDIM; c++) s[t][c] = 0.f;

    #pragma unroll
    for (int k = 0; k < 4; k++) {
        float4 xv[4];
        #pragma unroll
        for (int t = 0; t < 4; t++)
            xv[t] = ((const float4*)(x + (size_t)(token0 + t) * DIM))[k * 32 + l];
        #pragma unroll
        for (int c = 0; c < CDIM; c++) {
            float4 wv = win4[c * 128 + k * 32 + l];
            #pragma unroll
            for (int t = 0; t < 4; t++)
                s[t][c] += xv[t].x * wv.x + xv[t].y * wv.y
                         + xv[t].z * wv.z + xv[t].w * wv.w;
        }
    }

    // butterfly reductions (interleave tokens for ILP)
    #pragma unroll
    for (int c = 0; c < CDIM; c++) {
        #pragma unroll
        for (int off = 16; off; off >>= 1) {
            s[0][c] += __shfl_xor_sync(0xffffffffu, s[0][c], off);
            s[1][c] += __shfl_xor_sync(0xffffffffu, s[1][c], off);
            s[2][c] += __shfl_xor_sync(0xffffffffu, s[2][c], off);
            s[3][c] += __shfl_xor_sync(0xffffffffu, s[3][c], off);
        }
    }

    float commit_acc = 0.f;
    unsigned idx[4];
    #pragma unroll
    for (int t = 0; t < 4; t++) {
        idx[t] = 0;
        #pragma unroll
        for (int c = 0; c < CDIM; c++) {
            float p = s[t][c] + s_bin[c];
            bool pos = p > 0.f;
            idx[t] |= (pos ? 1u : 0u) << (13 - c);
            float sg = pos ? 1.f : -1.f;
            float d = p - sg;
            commit_acc += d * d;                  // identical in all lanes
            if (l == 0) sP[(tok0 + t) * 16 + c] = p;
            s[t][c] = sg;                         // reuse as sign
        }
        if (l == 0) idx_out[token0 + t] = (float)idx[t];
    }

    // ---- stage A part 2: project-out, 4 tokens jointly, k-outer
    #pragma unroll
    for (int k = 0; k < 4; k++) {
        float4 a[4];
        float4 bb = bout4[k * 32 + l];
        #pragma unroll
        for (int t = 0; t < 4; t++) a[t] = bb;
        #pragma unroll
        for (int c = 0; c < CDIM; c++) {
            float4 wv = wout4[c * 128 + k * 32 + l];
            #pragma unroll
            for (int t = 0; t < 4; t++) {
                a[t].x += s[t][c] * wv.x; a[t].y += s[t][c] * wv.y;
                a[t].z += s[t][c] * wv.z; a[t].w += s[t][c] * wv.w;
            }
        }
        #pragma unroll
        for (int t = 0; t < 4; t++)
            ((float4*)(out + (size_t)(token0 + t) * DIM))[k * 32 + l] = a[t];
    }
    __syncthreads();

    // ---- stage B: sigmoids + per-sample entropy partial
    float hloc = 0.f;
    for (int i = tid; i < 32 * CDIM; i += 256) {
        int tok = i / CDIM, c = i % CDIM;
        float p = sP[tok * 16 + c];
        float q = 1.f / (1.f + __expf(-400.f * p));
        sQ[tok * 16 + c] = q;
        float qm = 1.f - q;
        hloc += -(q  * __logf(fmaxf(q,  1e-20f)) +
                  qm * __logf(fmaxf(qm, 1e-20f)));
    }
    __syncthreads();

    // ---- stage C: factorized outer-product accumulation, 4 tokens/phase
    float acc[64];
    #pragma unroll
    for (int i = 0; i < 64; i++) acc[i] = 0.f;

    #pragma unroll 1
    for (int t = 0; t < 32; t += 4) {
        #pragma unroll
        for (int u = 0; u < 4; u++) {
            const float* q = &sQ[(t + u) * 16];
            if (tid < 128) {                       // A over c = 0..6 (bits 13..7)
                float v = 1.f;
                #pragma unroll
                for (int c = 0; c < 7; c++)
                    v *= ((tid >> (6 - c)) & 1) ? q[c] : (1.f - q[c]);
                sA[u][tid] = v;
            } else {                               // B over c = 7..13 (bits 6..0)
                int lo = tid - 128;
                float v = 1.f;
                #pragma unroll
                for (int c = 7; c < 14; c++)
                    v *= ((lo >> (13 - c)) & 1) ? q[c] : (1.f - q[c]);
                sB[u][lo] = v;
            }
        }
        __syncthreads();
        #pragma unroll
        for (int u = 0; u < 4; u++) {
            float4 bv = ((const float4*)sB[u])[l];           // lane-varying
            const float4* ap = (const float4*)&sA[u][w * 16]; // warp-broadcast
            float4 aa[4];
            aa[0] = ap[0]; aa[1] = ap[1]; aa[2] = ap[2]; aa[3] = ap[3];
            const float* av = (const float*)aa;
            #pragma unroll
            for (int i = 0; i < 16; i++) {
                float a = av[i];
                acc[4*i+0] += a * bv.x;
                acc[4*i+1] += a * bv.y;
                acc[4*i+2] += a * bv.z;
                acc[4*i+3] += a * bv.w;
            }
        }
        __syncthreads();
    }

    // ---- epilogue: coalesced partial writes (code j = w*2048 + i*128 + l*4 + k)
    float4* dst = (float4*)(g_part + (size_t)blockIdx.x * KSIZE + w * 2048);
    #pragma unroll
    for (int i = 0; i < 16; i++)
        dst[i * 32 + l] = make_float4(acc[4*i], acc[4*i+1], acc[4*i+2], acc[4*i+3]);

    // ---- block scalar reductions
    #pragma unroll
    for (int off = 16; off; off >>= 1) hloc += __shfl_xor_sync(0xffffffffu, hloc, off);
    if (l == 0) { sred[w] = commit_acc; sred[8 + w] = hloc; }
    __syncthreads();
    if (tid == 0) {
        float c = 0.f, h = 0.f;
        #pragma unroll
        for (int i = 0; i < 8; i++) { c += sred[i]; h += sred[8 + i]; }
        g_sc[blockIdx.x] = c;
        g_se[blockIdx.x] = h;
    }
}

// ---------------------------------------------------------------- K3a: reduce partials -> codebook entropy partials
__global__ __launch_bounds__(256) void k3a(float inv_ntok) {
    int gid = blockIdx.x * 256 + threadIdx.x;     // code index, grid=64
    const float* p = g_part + gid;
    float a0 = 0.f, a1 = 0.f, a2 = 0.f, a3 = 0.f;
    #pragma unroll 4
    for (int b = 0; b < NBLK; b += 4) {
        a0 += p[(size_t)(b    ) * KSIZE];
        a1 += p[(size_t)(b + 1) * KSIZE];
        a2 += p[(size_t)(b + 2) * KSIZE];
        a3 += p[(size_t)(b + 3) * KSIZE];
    }
    float a = ((a0 + a1) + (a2 + a3)) * inv_ntok;
    float s = -a * __logf(fmaxf(a, 1e-20f));

    __shared__ float sred[8];
    #pragma unroll
    for (int off = 16; off; off >>= 1) s += __shfl_xor_sync(0xffffffffu, s, off);
    if ((threadIdx.x & 31) == 0) sred[threadIdx.x >> 5] = s;
    __syncthreads();
    if (threadIdx.x == 0) {
        float t = 0.f;
        #pragma unroll
        for (int i = 0; i < 8; i++) t += sred[i];
        g_hc[blockIdx.x] = t;
    }
}

// ---------------------------------------------------------------- K3b: final scalar
__global__ __launch_bounds__(256) void k3b(float* __restrict__ aux_out, float inv_ntok) {
    int tid = threadIdx.x;
    float hc = (tid < 64) ? g_hc[tid] : 0.f;
    float sc = g_sc[tid];
    float se = g_se[tid];
    #pragma unroll
    for (int off = 16; off; off >>= 1) {
        hc += __shfl_xor_sync(0xffffffffu, hc, off);
        sc += __shfl_xor_sync(0xffffffffu, sc, off);
        se += __shfl_xor_sync(0xffffffffu, se, off);
    }
    __shared__ float sr[3][8];
    int w = tid >> 5;
    if ((tid & 31) == 0) { sr[0][w] = hc; sr[1][w] = sc; sr[2][w] = se; }
    __syncthreads();
    if (tid == 0) {
        float Hc = 0.f, C = 0.f, Hs = 0.f;
        #pragma unroll
        for (int i = 0; i < 8; i++) { Hc += sr[0][i]; C += sr[1][i]; Hs += sr[2][i]; }
        float per_sample = Hs * inv_ntok;
        float commit = C * inv_ntok * (1.f / (float)CDIM);
        *aux_out = 0.1f * (per_sample - Hc) + 0.25f * commit;
    }
}

// ----------------------------------------------------------------
extern "C" void kernel_launch(void* const* d_in, const int* in_sizes, int n_in,
                              void* d_out, int out_size) {
    const float* x     = (const float*)d_in[0];
    const float* w_in  = (const float*)d_in[1];
    const float* b_in  = (const float*)d_in[2];
    const float* w_out = (const float*)d_in[3];
    const float* b_out = (const float*)d_in[4];

    int ntok = in_sizes[0] / DIM;               // 8192
    float* out     = (float*)d_out;
    float* idx_out = out + (size_t)ntok * DIM;
    float* aux_out = idx_out + ntok;

    float inv_ntok = 1.f / (float)ntok;

    kF<<<ntok / 32, 256>>>(x, w_in, b_in, w_out, b_out, out, idx_out);
    k3a<<<64, 256>>>(inv_ntok);
    k3b<<<1, 256>>>(aux_out, inv_ntok);
}

// round 7
// speedup vs baseline: 3.3080x; 1.1604x over previous
#include <cuda_runtime.h>
#include <math.h>

#define DIM     512
#define CDIM    14
#define KSIZE   16384
#define NBLK    256      // 8192 tokens / 32 per block
#define WOPITCH 520      // padded s_wout row pitch (8 mod 32 -> conflict-light)

// scratch — static device globals (no allocation allowed)
__device__ float g_part[NBLK * KSIZE];   // per-block partial prob sums (16MB)
__device__ float g_sc[NBLK];             // per-block commit partial
__device__ float g_se[NBLK];             // per-block sample-entropy partial
__device__ float g_hc[64];               // per-block codebook-entropy partial
__device__ int   g_done;                 // last-block-done counter (self-resetting)

// ---------------------------------------------------------------- fused kernel
// grid = 256 blocks x 256 threads; block owns 32 tokens (4 per warp).
// Stage A: k-outer 4-token projection; fold-reduction (9 shfl + 3 sel per c);
//          idx re-broadcast, signs from bits; project-out from padded smem.
// Stage B: q = sigmoid(400p), per-sample entropy partial.
// Stage C: 4 tokens/phase; q via broadcast float4; A table in registers.
__global__ __launch_bounds__(256, 2) void kF(
    const float* __restrict__ x,
    const float* __restrict__ w_in,   // [14][512]
    const float* __restrict__ b_in,   // [14]
    const float* __restrict__ w_out,  // [512][14]
    const float* __restrict__ b_out,  // [512]
    float* __restrict__ out,
    float* __restrict__ idx_out)
{
    __shared__ float s_wout[CDIM * WOPITCH];   // transposed, padded [c*520+d]
    __shared__ float s_bin[16];
    __shared__ float sQ[32 * 16];              // sigmoid values [tok*16+c]
    __shared__ float sP[32 * 16];              // p values
    __shared__ __align__(16) float sA[4][128];
    __shared__ __align__(16) float sB[4][128];
    __shared__ float sred[16];

    int tid = threadIdx.x;
    for (int i = tid; i < CDIM * DIM; i += 256) {
        int d = i / CDIM, c = i % CDIM;
        s_wout[c * WOPITCH + d] = w_out[i];
    }
    if (tid < CDIM) s_bin[tid] = b_in[tid];
    __syncthreads();

    int w = tid >> 5, l = tid & 31;
    const float4* win4  = (const float4*)w_in;
    const float4* wout4 = (const float4*)s_wout;   // row stride 130 float4
    const float4* bout4 = (const float4*)b_out;

    int tok0   = w * 4;
    int token0 = blockIdx.x * 32 + tok0;

    // ---- stage A part 1: projection, 4 tokens jointly, k-outer
    float s0[CDIM], s1[CDIM], s2[CDIM], s3[CDIM];
    #pragma unroll
    for (int c = 0; c < CDIM; c++) { s0[c]=0.f; s1[c]=0.f; s2[c]=0.f; s3[c]=0.f; }

    #pragma unroll
    for (int k = 0; k < 4; k++) {
        float4 xv0 = ((const float4*)(x + (size_t)(token0    ) * DIM))[k * 32 + l];
        float4 xv1 = ((const float4*)(x + (size_t)(token0 + 1) * DIM))[k * 32 + l];
        float4 xv2 = ((const float4*)(x + (size_t)(token0 + 2) * DIM))[k * 32 + l];
        float4 xv3 = ((const float4*)(x + (size_t)(token0 + 3) * DIM))[k * 32 + l];
        #pragma unroll
        for (int c = 0; c < CDIM; c++) {
            float4 wv = win4[c * 128 + k * 32 + l];
            s0[c] += xv0.x*wv.x + xv0.y*wv.y + xv0.z*wv.z + xv0.w*wv.w;
            s1[c] += xv1.x*wv.x + xv1.y*wv.y + xv1.z*wv.z + xv1.w*wv.w;
            s2[c] += xv2.x*wv.x + xv2.y*wv.y + xv2.z*wv.z + xv2.w*wv.w;
            s3[c] += xv3.x*wv.x + xv3.y*wv.y + xv3.z*wv.z + xv3.w*wv.w;
        }
    }

    // fold reduction: 9 shfl + 3 sel per c. Lane group g = l>>3 owns token g.
    float pv[CDIM];
    #pragma unroll
    for (int c = 0; c < CDIM; c++) {
        float t0 = s0[c], t1 = s1[c], t2 = s2[c], t3 = s3[c];
        t0 += __shfl_xor_sync(0xffffffffu, t0, 16);
        t1 += __shfl_xor_sync(0xffffffffu, t1, 16);
        t2 += __shfl_xor_sync(0xffffffffu, t2, 16);
        t3 += __shfl_xor_sync(0xffffffffu, t3, 16);
        float a = (l < 16) ? t0 : t2;
        float b = (l < 16) ? t1 : t3;
        a += __shfl_xor_sync(0xffffffffu, a, 8);
        b += __shfl_xor_sync(0xffffffffu, b, 8);
        float m = (l & 8) ? b : a;
        m += __shfl_xor_sync(0xffffffffu, m, 4);
        m += __shfl_xor_sync(0xffffffffu, m, 2);
        m += __shfl_xor_sync(0xffffffffu, m, 1);
        pv[c] = m + s_bin[c];
    }

    int g = l >> 3;
    unsigned idx = 0;
    float commit = 0.f;
    #pragma unroll
    for (int c = 0; c < CDIM; c++) {
        bool pos = pv[c] > 0.f;
        idx |= (pos ? 1u : 0u) << (13 - c);
        float sg = pos ? 1.f : -1.f;
        float d = pv[c] - sg;
        commit += d * d;
    }
    if ((l & 7) == 0) {
        idx_out[token0 + g] = (float)idx;
        #pragma unroll
        for (int c = 0; c < CDIM; c++) sP[(tok0 + g) * 16 + c] = pv[c];
    }

    // broadcast token indices; commit reduce over the 4 groups
    unsigned idxs[4];
    #pragma unroll
    for (int t = 0; t < 4; t++) idxs[t] = __shfl_sync(0xffffffffu, idx, t * 8);
    commit += __shfl_xor_sync(0xffffffffu, commit, 8);
    commit += __shfl_xor_sync(0xffffffffu, commit, 16);
    float commit_acc = commit;    // same in all lanes now

    float sg[4][CDIM];
    #pragma unroll
    for (int t = 0; t < 4; t++)
        #pragma unroll
        for (int c = 0; c < CDIM; c++)
            sg[t][c] = ((idxs[t] >> (13 - c)) & 1) ? 1.f : -1.f;

    // ---- stage A part 2: project-out, 4 tokens jointly, k-outer
    #pragma unroll
    for (int k = 0; k < 4; k++) {
        float4 bb = bout4[k * 32 + l];
        float4 a[4];
        #pragma unroll
        for (int t = 0; t < 4; t++) a[t] = bb;
        #pragma unroll
        for (int c = 0; c < CDIM; c++) {
            float4 wv = wout4[c * 130 + k * 32 + l];
            #pragma unroll
            for (int t = 0; t < 4; t++) {
                a[t].x += sg[t][c] * wv.x; a[t].y += sg[t][c] * wv.y;
                a[t].z += sg[t][c] * wv.z; a[t].w += sg[t][c] * wv.w;
            }
        }
        #pragma unroll
        for (int t = 0; t < 4; t++)
            ((float4*)(out + (size_t)(token0 + t) * DIM))[k * 32 + l] = a[t];
    }
    __syncthreads();

    // ---- stage B: sigmoids + per-sample entropy partial
    float hloc = 0.f;
    for (int i = tid; i < 32 * CDIM; i += 256) {
        int tok = i / CDIM, c = i % CDIM;
        float p = sP[tok * 16 + c];
        float q = 1.f / (1.f + __expf(-400.f * p));
        sQ[tok * 16 + c] = q;
        float qm = 1.f - q;
        hloc += -(q  * __logf(fmaxf(q,  1e-20f)) +
                  qm * __logf(fmaxf(qm, 1e-20f)));
    }
    __syncthreads();

    // ---- stage C: factorized outer-product accumulation, 4 tokens/phase
    float acc[64];
    #pragma unroll
    for (int i = 0; i < 64; i++) acc[i] = 0.f;

    #pragma unroll 1
    for (int t = 0; t < 32; t += 4) {
        #pragma unroll
        for (int u = 0; u < 4; u++) {
            const float4* q4 = (const float4*)&sQ[(t + u) * 16];
            if (tid < 128) {                       // A over c = 0..6 (bits 13..7)
                float4 qa = q4[0], qb = q4[1];
                float v = ((tid & 64) ? qa.x : 1.f - qa.x)
                        * ((tid & 32) ? qa.y : 1.f - qa.y)
                        * ((tid & 16) ? qa.z : 1.f - qa.z)
                        * ((tid &  8) ? qa.w : 1.f - qa.w)
                        * ((tid &  4) ? qb.x : 1.f - qb.x)
                        * ((tid &  2) ? qb.y : 1.f - qb.y)
                        * ((tid &  1) ? qb.z : 1.f - qb.z);
                sA[u][tid] = v;
            } else {                               // B over c = 7..13 (bits 6..0)
                int lo = tid - 128;
                float4 qb = q4[1], qc = q4[2], qd = q4[3];
                float v = ((lo & 64) ? qb.w : 1.f - qb.w)
                        * ((lo & 32) ? qc.x : 1.f - qc.x)
                        * ((lo & 16) ? qc.y : 1.f - qc.y)
                        * ((lo &  8) ? qc.z : 1.f - qc.z)
                        * ((lo &  4) ? qc.w : 1.f - qc.w)
                        * ((lo &  2) ? qd.x : 1.f - qd.x)
                        * ((lo &  1) ? qd.y : 1.f - qd.y);
                sB[u][lo] = v;
            }
        }
        __syncthreads();
        #pragma unroll
        for (int u = 0; u < 4; u++) {
            float4 bv = ((const float4*)sB[u])[l];            // lane-varying
            const float4* ap = (const float4*)&sA[u][w * 16]; // warp-broadcast
            float4 aa[4];
            aa[0] = ap[0]; aa[1] = ap[1]; aa[2] = ap[2]; aa[3] = ap[3];
            const float* av = (const float*)aa;
            #pragma unroll
            for (int i = 0; i < 16; i++) {
                float a = av[i];
                acc[4*i+0] += a * bv.x;
                acc[4*i+1] += a * bv.y;
                acc[4*i+2] += a * bv.z;
                acc[4*i+3] += a * bv.w;
            }
        }
        __syncthreads();
    }

    // ---- epilogue: coalesced partial writes (code j = w*2048 + i*128 + l*4 + k)
    float4* dst = (float4*)(g_part + (size_t)blockIdx.x * KSIZE + w * 2048);
    #pragma unroll
    for (int i = 0; i < 16; i++)
        dst[i * 32 + l] = make_float4(acc[4*i], acc[4*i+1], acc[4*i+2], acc[4*i+3]);

    // ---- block scalar reductions
    #pragma unroll
    for (int off = 16; off; off >>= 1) hloc += __shfl_xor_sync(0xffffffffu, hloc, off);
    if (l == 0) { sred[w] = commit_acc; sred[8 + w] = hloc; }
    __syncthreads();
    if (tid == 0) {
        float c = 0.f, h = 0.f;
        #pragma unroll
        for (int i = 0; i < 8; i++) { c += sred[i]; h += sred[8 + i]; }
        g_sc[blockIdx.x] = c;
        g_se[blockIdx.x] = h;
    }
}

// ---------------------------------------------------------------- K3: reduce partials -> aux (fused finisher)
__global__ __launch_bounds__(256) void k3(float* __restrict__ aux_out, float inv_ntok) {
    int tid = threadIdx.x;
    int gid = blockIdx.x * 256 + tid;             // code index, grid=64
    const float* p = g_part + gid;
    float a0 = 0.f, a1 = 0.f, a2 = 0.f, a3 = 0.f;
    #pragma unroll 4
    for (int b = 0; b < NBLK; b += 4) {
        a0 += p[(size_t)(b    ) * KSIZE];
        a1 += p[(size_t)(b + 1) * KSIZE];
        a2 += p[(size_t)(b + 2) * KSIZE];
        a3 += p[(size_t)(b + 3) * KSIZE];
    }
    float a = ((a0 + a1) + (a2 + a3)) * inv_ntok;
    float s = -a * __logf(fmaxf(a, 1e-20f));

    __shared__ float sred[8];
    #pragma unroll
    for (int off = 16; off; off >>= 1) s += __shfl_xor_sync(0xffffffffu, s, off);
    if ((tid & 31) == 0) sred[tid >> 5] = s;
    __syncthreads();
    if (tid == 0) {
        float t = 0.f;
        #pragma unroll
        for (int i = 0; i < 8; i++) t += sred[i];
        g_hc[blockIdx.x] = t;
    }

    // last-block-done: final scalar combine, counter self-resets for graph replay
    __threadfence();
    __shared__ int lastflag;
    if (tid == 0) lastflag = (atomicAdd(&g_done, 1) == 63);
    __syncthreads();
    if (lastflag) {
        float hc = (tid < 64) ? g_hc[tid] : 0.f;
        float sc = g_sc[tid];
        float se = g_se[tid];
        #pragma unroll
        for (int off = 16; off; off >>= 1) {
            hc += __shfl_xor_sync(0xffffffffu, hc, off);
            sc += __shfl_xor_sync(0xffffffffu, sc, off);
            se += __shfl_xor_sync(0xffffffffu, se, off);
        }
        __shared__ float sr[3][8];
        int w = tid >> 5;
        if ((tid & 31) == 0) { sr[0][w] = hc; sr[1][w] = sc; sr[2][w] = se; }
        __syncthreads();
        if (tid == 0) {
            float Hc = 0.f, C = 0.f, Hs = 0.f;
            #pragma unroll
            for (int i = 0; i < 8; i++) { Hc += sr[0][i]; C += sr[1][i]; Hs += sr[2][i]; }
            float per_sample = Hs * inv_ntok;
            float commit = C * inv_ntok * (1.f / (float)CDIM);
            *aux_out = 0.1f * (per_sample - Hc) + 0.25f * commit;
            g_done = 0;                       // reset for next launch/replay
        }
    }
}

// ----------------------------------------------------------------
extern "C" void kernel_launch(void* const* d_in, const int* in_sizes, int n_in,
                              void* d_out, int out_size) {
    const float* x     = (const float*)d_in[0];
    const float* w_in  = (const float*)d_in[1];
    const float* b_in  = (const float*)d_in[2];
    const float* w_out = (const float*)d_in[3];
    const float* b_out = (const float*)d_in[4];

    int ntok = in_sizes[0] / DIM;               // 8192
    float* out     = (float*)d_out;
    float* idx_out = out + (size_t)ntok * DIM;
    float* aux_out = idx_out + ntok;

    float inv_ntok = 1.f / (float)ntok;

    kF<<<ntok / 32, 256>>>(x, w_in, b_in, w_out, b_out, out, idx_out);
    k3<<<64, 256>>>(aux_out, inv_ntok);
}

// round 9
// speedup vs baseline: 3.6789x; 1.1121x over previous
#include <cuda_runtime.h>
#include <math.h>

#define DIM     512
#define CDIM    14
#define KSIZE   16384
#define NBLK    256      // 8192 tokens / 32 per block
#define WOPITCH 520      // padded s_wout row pitch (8 mod 32 -> conflict-light)
#define R3BLK   256      // k3 grid

// scratch — static device globals (no allocation allowed)
__device__ float g_part[NBLK * KSIZE];   // per-block partial prob sums (16MB)
__device__ float g_sc[NBLK];             // per-block commit partial
__device__ float g_se[NBLK];             // per-block sample-entropy partial
__device__ float g_hc[R3BLK];            // per-k3-block codebook-entropy partial
__device__ int   g_done;                 // last-block-done counter (self-resetting)

// ---------------------------------------------------------------- fused kernel
// grid = 256 blocks x 256 threads; block owns 32 tokens (4 per warp).
__global__ __launch_bounds__(256, 2) void kF(
    const float* __restrict__ x,
    const float* __restrict__ w_in,   // [14][512]
    const float* __restrict__ b_in,   // [14]
    const float* __restrict__ w_out,  // [512][14]
    const float* __restrict__ b_out,  // [512]
    float* __restrict__ out,
    float* __restrict__ idx_out)
{
    __shared__ float s_wout[CDIM * WOPITCH];   // transposed, padded [c*520+d]
    __shared__ float s_bin[16];
    __shared__ float sQ[32 * 16];              // sigmoid values [tok*16+c]
    __shared__ float sP[32 * 16];              // p values
    __shared__ __align__(16) float sA[4][128];
    __shared__ __align__(16) float sB[4][128];
    __shared__ float sred[16];

    int tid = threadIdx.x;
    for (int i = tid; i < CDIM * DIM; i += 256) {
        int d = i / CDIM, c = i % CDIM;
        s_wout[c * WOPITCH + d] = w_out[i];
    }
    if (tid < CDIM) s_bin[tid] = b_in[tid];
    __syncthreads();

    int w = tid >> 5, l = tid & 31;
    const float4* win4  = (const float4*)w_in;
    const float4* wout4 = (const float4*)s_wout;   // row stride 130 float4
    const float4* bout4 = (const float4*)b_out;

    int tok0   = w * 4;
    int token0 = blockIdx.x * 32 + tok0;

    // ---- stage A part 1: projection, 4 tokens jointly, k-outer
    float s0[CDIM], s1[CDIM], s2[CDIM], s3[CDIM];
    #pragma unroll
    for (int c = 0; c < CDIM; c++) { s0[c]=0.f; s1[c]=0.f; s2[c]=0.f; s3[c]=0.f; }

    #pragma unroll
    for (int k = 0; k < 4; k++) {
        float4 xv0 = ((const float4*)(x + (size_t)(token0    ) * DIM))[k * 32 + l];
        float4 xv1 = ((const float4*)(x + (size_t)(token0 + 1) * DIM))[k * 32 + l];
        float4 xv2 = ((const float4*)(x + (size_t)(token0 + 2) * DIM))[k * 32 + l];
        float4 xv3 = ((const float4*)(x + (size_t)(token0 + 3) * DIM))[k * 32 + l];
        #pragma unroll
        for (int c = 0; c < CDIM; c++) {
            float4 wv = win4[c * 128 + k * 32 + l];
            s0[c] += xv0.x*wv.x + xv0.y*wv.y + xv0.z*wv.z + xv0.w*wv.w;
            s1[c] += xv1.x*wv.x + xv1.y*wv.y + xv1.z*wv.z + xv1.w*wv.w;
            s2[c] += xv2.x*wv.x + xv2.y*wv.y + xv2.z*wv.z + xv2.w*wv.w;
            s3[c] += xv3.x*wv.x + xv3.y*wv.y + xv3.z*wv.z + xv3.w*wv.w;
        }
    }

    // fold reduction: 9 shfl + 3 sel per c. Lane group g = l>>3 owns token g.
    float pv[CDIM];
    #pragma unroll
    for (int c = 0; c < CDIM; c++) {
        float t0 = s0[c], t1 = s1[c], t2 = s2[c], t3 = s3[c];
        t0 += __shfl_xor_sync(0xffffffffu, t0, 16);
        t1 += __shfl_xor_sync(0xffffffffu, t1, 16);
        t2 += __shfl_xor_sync(0xffffffffu, t2, 16);
        t3 += __shfl_xor_sync(0xffffffffu, t3, 16);
        float a = (l < 16) ? t0 : t2;
        float b = (l < 16) ? t1 : t3;
        a += __shfl_xor_sync(0xffffffffu, a, 8);
        b += __shfl_xor_sync(0xffffffffu, b, 8);
        float m = (l & 8) ? b : a;
        m += __shfl_xor_sync(0xffffffffu, m, 4);
        m += __shfl_xor_sync(0xffffffffu, m, 2);
        m += __shfl_xor_sync(0xffffffffu, m, 1);
        pv[c] = m + s_bin[c];
    }

    int g = l >> 3;
    unsigned idx = 0;
    float commit = 0.f;
    #pragma unroll
    for (int c = 0; c < CDIM; c++) {
        bool pos = pv[c] > 0.f;
        idx |= (pos ? 1u : 0u) << (13 - c);
        float sg = pos ? 1.f : -1.f;
        float d = pv[c] - sg;
        commit += d * d;
    }
    if ((l & 7) == 0) {
        idx_out[token0 + g] = (float)idx;
        #pragma unroll
        for (int c = 0; c < CDIM; c++) sP[(tok0 + g) * 16 + c] = pv[c];
    }

    // broadcast token indices; commit reduce over the 4 groups
    unsigned idxs[4];
    #pragma unroll
    for (int t = 0; t < 4; t++) idxs[t] = __shfl_sync(0xffffffffu, idx, t * 8);
    commit += __shfl_xor_sync(0xffffffffu, commit, 8);
    commit += __shfl_xor_sync(0xffffffffu, commit, 16);
    float commit_acc = commit;    // same in all lanes now

    float sg[4][CDIM];
    #pragma unroll
    for (int t = 0; t < 4; t++)
        #pragma unroll
        for (int c = 0; c < CDIM; c++)
            sg[t][c] = ((idxs[t] >> (13 - c)) & 1) ? 1.f : -1.f;

    // ---- stage A part 2: project-out, 4 tokens jointly, k-outer
    #pragma unroll
    for (int k = 0; k < 4; k++) {
        float4 bb = bout4[k * 32 + l];
        float4 a[4];
        #pragma unroll
        for (int t = 0; t < 4; t++) a[t] = bb;
        #pragma unroll
        for (int c = 0; c < CDIM; c++) {
            float4 wv = wout4[c * 130 + k * 32 + l];
            #pragma unroll
            for (int t = 0; t < 4; t++) {
                a[t].x += sg[t][c] * wv.x; a[t].y += sg[t][c] * wv.y;
                a[t].z += sg[t][c] * wv.z; a[t].w += sg[t][c] * wv.w;
            }
        }
        #pragma unroll
        for (int t = 0; t < 4; t++)
            ((float4*)(out + (size_t)(token0 + t) * DIM))[k * 32 + l] = a[t];
    }
    __syncthreads();

    // ---- stage B: sigmoids + per-sample entropy partial
    float hloc = 0.f;
    for (int i = tid; i < 32 * CDIM; i += 256) {
        int tok = i / CDIM, c = i % CDIM;
        float p = sP[tok * 16 + c];
        float q = 1.f / (1.f + __expf(-400.f * p));
        sQ[tok * 16 + c] = q;
        float qm = 1.f - q;
        hloc += -(q  * __logf(fmaxf(q,  1e-20f)) +
                  qm * __logf(fmaxf(qm, 1e-20f)));
    }
    __syncthreads();

    // ---- stage C: factorized outer-product accumulation, 4 tokens/phase
    float acc[64];
    #pragma unroll
    for (int i = 0; i < 64; i++) acc[i] = 0.f;

    #pragma unroll 1
    for (int t = 0; t < 32; t += 4) {
        #pragma unroll
        for (int u = 0; u < 4; u++) {
            const float4* q4 = (const float4*)&sQ[(t + u) * 16];
            if (tid < 128) {                       // A over c = 0..6 (bits 13..7)
                float4 qa = q4[0], qb = q4[1];
                float v = ((tid & 64) ? qa.x : 1.f - qa.x)
                        * ((tid & 32) ? qa.y : 1.f - qa.y)
                        * ((tid & 16) ? qa.z : 1.f - qa.z)
                        * ((tid &  8) ? qa.w : 1.f - qa.w)
                        * ((tid &  4) ? qb.x : 1.f - qb.x)
                        * ((tid &  2) ? qb.y : 1.f - qb.y)
                        * ((tid &  1) ? qb.z : 1.f - qb.z);
                sA[u][tid] = v;
            } else {                               // B over c = 7..13 (bits 6..0)
                int lo = tid - 128;
                float4 qb = q4[1], qc = q4[2], qd = q4[3];
                float v = ((lo & 64) ? qb.w : 1.f - qb.w)
                        * ((lo & 32) ? qc.x : 1.f - qc.x)
                        * ((lo & 16) ? qc.y : 1.f - qc.y)
                        * ((lo &  8) ? qc.z : 1.f - qc.z)
                        * ((lo &  4) ? qc.w : 1.f - qc.w)
                        * ((lo &  2) ? qd.x : 1.f - qd.x)
                        * ((lo &  1) ? qd.y : 1.f - qd.y);
                sB[u][lo] = v;
            }
        }
        __syncthreads();
        #pragma unroll
        for (int u = 0; u < 4; u++) {
            float4 bv = ((const float4*)sB[u])[l];            // lane-varying
            const float4* ap = (const float4*)&sA[u][w * 16]; // warp-broadcast
            float4 aa[4];
            aa[0] = ap[0]; aa[1] = ap[1]; aa[2] = ap[2]; aa[3] = ap[3];
            const float* av = (const float*)aa;
            #pragma unroll
            for (int i = 0; i < 16; i++) {
                float a = av[i];
                acc[4*i+0] += a * bv.x;
                acc[4*i+1] += a * bv.y;
                acc[4*i+2] += a * bv.z;
                acc[4*i+3] += a * bv.w;
            }
        }
        __syncthreads();
    }

    // ---- epilogue: coalesced partial writes (code j = w*2048 + i*128 + l*4 + k)
    float4* dst = (float4*)(g_part + (size_t)blockIdx.x * KSIZE + w * 2048);
    #pragma unroll
    for (int i = 0; i < 16; i++)
        dst[i * 32 + l] = make_float4(acc[4*i], acc[4*i+1], acc[4*i+2], acc[4*i+3]);

    // ---- block scalar reductions
    #pragma unroll
    for (int off = 16; off; off >>= 1) hloc += __shfl_xor_sync(0xffffffffu, hloc, off);
    if (l == 0) { sred[w] = commit_acc; sred[8 + w] = hloc; }
    __syncthreads();
    if (tid == 0) {
        float c = 0.f, h = 0.f;
        #pragma unroll
        for (int i = 0; i < 8; i++) { c += sred[i]; h += sred[8 + i]; }
        g_sc[blockIdx.x] = c;
        g_se[blockIdx.x] = h;
    }
}

// ---------------------------------------------------------------- K3: reduce partials -> aux
// grid = 256 blocks x 256 threads. Block bx owns codes [bx*64, bx*64+64).
// Thread: code = bx*64 + (tid&63), chunk = tid>>6 sums 64 block-partials
// (fully unrolled, 8 accumulators for deep MLP). Chunk-combine via smem,
// entropy on 64 lanes, last-block finisher (counter self-resets).
__global__ __launch_bounds__(256) void k3(float* __restrict__ aux_out, float inv_ntok) {
    int tid = threadIdx.x;
    int code = blockIdx.x * 64 + (tid & 63);
    int chunk = tid >> 6;                         // 0..3
    const float* p = g_part + (size_t)chunk * 64 * KSIZE + code;

    float a0=0.f,a1=0.f,a2=0.f,a3=0.f,a4=0.f,a5=0.f,a6=0.f,a7=0.f;
    #pragma unroll
    for (int b = 0; b < 64; b += 8) {
        a0 += p[(size_t)(b    ) * KSIZE];
        a1 += p[(size_t)(b + 1) * KSIZE];
        a2 += p[(size_t)(b + 2) * KSIZE];
        a3 += p[(size_t)(b + 3) * KSIZE];
        a4 += p[(size_t)(b + 4) * KSIZE];
        a5 += p[(size_t)(b + 5) * KSIZE];
        a6 += p[(size_t)(b + 6) * KSIZE];
        a7 += p[(size_t)(b + 7) * KSIZE];
    }
    float v = ((a0 + a1) + (a2 + a3)) + ((a4 + a5) + (a6 + a7));

    __shared__ float sp[4][64];
    sp[chunk][tid & 63] = v;
    __syncthreads();

    float s = 0.f;
    if (tid < 64) {
        float a = (sp[0][tid] + sp[1][tid] + sp[2][tid] + sp[3][tid]) * inv_ntok;
        s = -a * __logf(fmaxf(a, 1e-20f));
    }
    #pragma unroll
    for (int off = 16; off; off >>= 1) s += __shfl_xor_sync(0xffffffffu, s, off);
    __shared__ float sw[2];
    if (tid == 0)  sw[0] = s;
    if (tid == 32) sw[1] = s;
    __syncthreads();
    if (tid == 0) g_hc[blockIdx.x] = sw[0] + sw[1];

    // last-block-done finisher
    __threadfence();
    __shared__ int lastflag;
    if (tid == 0) lastflag = (atomicAdd(&g_done, 1) == R3BLK - 1);
    __syncthreads();
    if (lastflag) {
        float hc = g_hc[tid];     // R3BLK == 256 entries
        float sc = g_sc[tid];
        float se = g_se[tid];
        #pragma unroll
        for (int off = 16; off; off >>= 1) {
            hc += __shfl_xor_sync(0xffffffffu, hc, off);
            sc += __shfl_xor_sync(0xffffffffu, sc, off);
            se += __shfl_xor_sync(0xffffffffu, se, off);
        }
        __shared__ float sr[3][8];
        int w = tid >> 5;
        if ((tid & 31) == 0) { sr[0][w] = hc; sr[1][w] = sc; sr[2][w] = se; }
        __syncthreads();
        if (tid == 0) {
            float Hc = 0.f, C = 0.f, Hs = 0.f;
            #pragma unroll
            for (int i = 0; i < 8; i++) { Hc += sr[0][i]; C += sr[1][i]; Hs += sr[2][i]; }
            float per_sample = Hs * inv_ntok;
            float commit = C * inv_ntok * (1.f / (float)CDIM);
            *aux_out = 0.1f * (per_sample - Hc) + 0.25f * commit;
            g_done = 0;                       // reset for next launch/replay
        }
    }
}

// ----------------------------------------------------------------
extern "C" void kernel_launch(void* const* d_in, const int* in_sizes, int n_in,
                              void* d_out, int out_size) {
    const float* x     = (const float*)d_in[0];
    const float* w_in  = (const float*)d_in[1];
    const float* b_in  = (const float*)d_in[2];
    const float* w_out = (const float*)d_in[3];
    const float* b_out = (const float*)d_in[4];

    int ntok = in_sizes[0] / DIM;               // 8192
    float* out     = (float*)d_out;
    float* idx_out = out + (size_t)ntok * DIM;
    float* aux_out = idx_out + ntok;

    float inv_ntok = 1.f / (float)ntok;

    kF<<<ntok / 32, 256>>>(x, w_in, b_in, w_out, b_out, out, idx_out);
    k3<<<R3BLK, 256>>>(aux_out, inv_ntok);
}

// round 10
// speedup vs baseline: 3.7555x; 1.0208x over previous
#include <cuda_runtime.h>
#include <math.h>

#define DIM     512
#define CDIM    14
#define KSIZE   16384
#define NBLK    256      // 8192 tokens / 32 per block
#define WOPITCH 520      // padded s_wout row pitch (8 mod 32 -> conflict-light)
#define R3BLK   512      // k3 grid

// scratch — static device globals (no allocation allowed)
__device__ float g_part[NBLK * KSIZE];   // per-block partial prob sums (16MB)
__device__ float g_sc[NBLK];             // per-block commit partial
__device__ float g_se[NBLK];             // per-block sample-entropy partial
__device__ float g_hc[R3BLK];            // per-k3-block codebook-entropy partial
__device__ int   g_done;                 // last-block-done counter (self-resetting)

// ---------------------------------------------------------------- fused kernel
// grid = 256 blocks x 256 threads; block owns 32 tokens (4 per warp).
// Stage A: k-outer 4-token projection + fold reduction + project-out.
// Stage B: q = sigmoid(400p) in place, per-sample entropy partial.
// Stage C: build ALL 32 token factor tables into smem (unioned with the dead
//          s_wout region), ONE barrier, then a barrier-free 2048-FFMA consume.
__global__ __launch_bounds__(256, 2) void kF(
    const float* __restrict__ x,
    const float* __restrict__ w_in,   // [14][512]
    const float* __restrict__ b_in,   // [14]
    const float* __restrict__ w_out,  // [512][14]
    const float* __restrict__ b_out,  // [512]
    float* __restrict__ out,
    float* __restrict__ idx_out)
{
    // blob: stage A = s_wout (CDIM*WOPITCH = 7280 used);
    //       stage C = tA[32][128] | tB[32][128] (8192 used)
    __shared__ __align__(16) float blob[8192];
    __shared__ float s_bin[16];
    __shared__ float sQ[32 * 16];              // p, then sigmoid(p) in place
    __shared__ float sred[16];

    float* s_wout = blob;                      // transposed, padded [c*520+d]
    float* tA = blob;                          // [tok*128 + hi]
    float* tB = blob + 4096;                   // [tok*128 + lo]

    int tid = threadIdx.x;
    for (int i = tid; i < CDIM * DIM; i += 256) {
        int d = i / CDIM, c = i % CDIM;
        s_wout[c * WOPITCH + d] = w_out[i];
    }
    if (tid < CDIM) s_bin[tid] = b_in[tid];
    __syncthreads();

    int w = tid >> 5, l = tid & 31;
    const float4* win4  = (const float4*)w_in;
    const float4* wout4 = (const float4*)s_wout;   // row stride 130 float4
    const float4* bout4 = (const float4*)b_out;

    int tok0   = w * 4;
    int token0 = blockIdx.x * 32 + tok0;

    // ---- stage A part 1: projection, 4 tokens jointly, k-outer
    float s0[CDIM], s1[CDIM], s2[CDIM], s3[CDIM];
    #pragma unroll
    for (int c = 0; c < CDIM; c++) { s0[c]=0.f; s1[c]=0.f; s2[c]=0.f; s3[c]=0.f; }

    #pragma unroll
    for (int k = 0; k < 4; k++) {
        float4 xv0 = ((const float4*)(x + (size_t)(token0    ) * DIM))[k * 32 + l];
        float4 xv1 = ((const float4*)(x + (size_t)(token0 + 1) * DIM))[k * 32 + l];
        float4 xv2 = ((const float4*)(x + (size_t)(token0 + 2) * DIM))[k * 32 + l];
        float4 xv3 = ((const float4*)(x + (size_t)(token0 + 3) * DIM))[k * 32 + l];
        #pragma unroll
        for (int c = 0; c < CDIM; c++) {
            float4 wv = win4[c * 128 + k * 32 + l];
            s0[c] += xv0.x*wv.x + xv0.y*wv.y + xv0.z*wv.z + xv0.w*wv.w;
            s1[c] += xv1.x*wv.x + xv1.y*wv.y + xv1.z*wv.z + xv1.w*wv.w;
            s2[c] += xv2.x*wv.x + xv2.y*wv.y + xv2.z*wv.z + xv2.w*wv.w;
            s3[c] += xv3.x*wv.x + xv3.y*wv.y + xv3.z*wv.z + xv3.w*wv.w;
        }
    }

    // fold reduction: 9 shfl + 3 sel per c. Lane group g = l>>3 owns token g.
    float pv[CDIM];
    #pragma unroll
    for (int c = 0; c < CDIM; c++) {
        float t0 = s0[c], t1 = s1[c], t2 = s2[c], t3 = s3[c];
        t0 += __shfl_xor_sync(0xffffffffu, t0, 16);
        t1 += __shfl_xor_sync(0xffffffffu, t1, 16);
        t2 += __shfl_xor_sync(0xffffffffu, t2, 16);
        t3 += __shfl_xor_sync(0xffffffffu, t3, 16);
        float a = (l < 16) ? t0 : t2;
        float b = (l < 16) ? t1 : t3;
        a += __shfl_xor_sync(0xffffffffu, a, 8);
        b += __shfl_xor_sync(0xffffffffu, b, 8);
        float m = (l & 8) ? b : a;
        m += __shfl_xor_sync(0xffffffffu, m, 4);
        m += __shfl_xor_sync(0xffffffffu, m, 2);
        m += __shfl_xor_sync(0xffffffffu, m, 1);
        pv[c] = m + s_bin[c];
    }

    int g = l >> 3;
    unsigned idx = 0;
    float commit = 0.f;
    #pragma unroll
    for (int c = 0; c < CDIM; c++) {
        bool pos = pv[c] > 0.f;
        idx |= (pos ? 1u : 0u) << (13 - c);
        float sg = pos ? 1.f : -1.f;
        float d = pv[c] - sg;
        commit += d * d;
    }
    if ((l & 7) == 0) {
        idx_out[token0 + g] = (float)idx;
        #pragma unroll
        for (int c = 0; c < CDIM; c++) sQ[(tok0 + g) * 16 + c] = pv[c];
    }

    // broadcast token indices; commit reduce over the 4 groups
    unsigned idxs[4];
    #pragma unroll
    for (int t = 0; t < 4; t++) idxs[t] = __shfl_sync(0xffffffffu, idx, t * 8);
    commit += __shfl_xor_sync(0xffffffffu, commit, 8);
    commit += __shfl_xor_sync(0xffffffffu, commit, 16);
    float commit_acc = commit;    // same in all lanes now

    float sg[4][CDIM];
    #pragma unroll
    for (int t = 0; t < 4; t++)
        #pragma unroll
        for (int c = 0; c < CDIM; c++)
            sg[t][c] = ((idxs[t] >> (13 - c)) & 1) ? 1.f : -1.f;

    // ---- stage A part 2: project-out, 4 tokens jointly, k-outer
    #pragma unroll
    for (int k = 0; k < 4; k++) {
        float4 bb = bout4[k * 32 + l];
        float4 a[4];
        #pragma unroll
        for (int t = 0; t < 4; t++) a[t] = bb;
        #pragma unroll
        for (int c = 0; c < CDIM; c++) {
            float4 wv = wout4[c * 130 + k * 32 + l];
            #pragma unroll
            for (int t = 0; t < 4; t++) {
                a[t].x += sg[t][c] * wv.x; a[t].y += sg[t][c] * wv.y;
                a[t].z += sg[t][c] * wv.z; a[t].w += sg[t][c] * wv.w;
            }
        }
        #pragma unroll
        for (int t = 0; t < 4; t++)
            ((float4*)(out + (size_t)(token0 + t) * DIM))[k * 32 + l] = a[t];
    }
    __syncthreads();    // sQ(p) complete; s_wout reads complete (blob reusable after next barrier)

    // ---- stage B: sigmoids (in place) + per-sample entropy partial
    float hloc = 0.f;
    for (int i = tid; i < 32 * CDIM; i += 256) {
        int tok = i / CDIM, c = i % CDIM;
        float p = sQ[tok * 16 + c];
        float q = 1.f / (1.f + __expf(-400.f * p));
        sQ[tok * 16 + c] = q;
        float qm = 1.f - q;
        hloc += -(q  * __logf(fmaxf(q,  1e-20f)) +
                  qm * __logf(fmaxf(qm, 1e-20f)));
    }
    __syncthreads();    // q ready; s_wout fully dead -> blob becomes tables

    // ---- stage C build: all 32 token tables, one pass
    #pragma unroll 1
    for (int t = 0; t < 32; t++) {
        const float4* q4 = (const float4*)&sQ[t * 16];
        if (tid < 128) {                       // A over c = 0..6 (bits 13..7)
            float4 qa = q4[0], qb = q4[1];
            float v = ((tid & 64) ? qa.x : 1.f - qa.x)
                    * ((tid & 32) ? qa.y : 1.f - qa.y)
                    * ((tid & 16) ? qa.z : 1.f - qa.z)
                    * ((tid &  8) ? qa.w : 1.f - qa.w)
                    * ((tid &  4) ? qb.x : 1.f - qb.x)
                    * ((tid &  2) ? qb.y : 1.f - qb.y)
                    * ((tid &  1) ? qb.z : 1.f - qb.z);
            tA[t * 128 + tid] = v;
        } else {                               // B over c = 7..13 (bits 6..0)
            int lo = tid - 128;
            float4 qb = q4[1], qc = q4[2], qd = q4[3];
            float v = ((lo & 64) ? qb.w : 1.f - qb.w)
                    * ((lo & 32) ? qc.x : 1.f - qc.x)
                    * ((lo & 16) ? qc.y : 1.f - qc.y)
                    * ((lo &  8) ? qc.z : 1.f - qc.z)
                    * ((lo &  4) ? qc.w : 1.f - qc.w)
                    * ((lo &  2) ? qd.x : 1.f - qd.x)
                    * ((lo &  1) ? qd.y : 1.f - qd.y);
            tB[t * 128 + lo] = v;
        }
    }
    __syncthreads();    // the only stage C barrier

    // ---- stage C consume: barrier-free FFMA stream
    float acc[64];
    #pragma unroll
    for (int i = 0; i < 64; i++) acc[i] = 0.f;

    #pragma unroll 2
    for (int t = 0; t < 32; t++) {
        float4 bv = ((const float4*)&tB[t * 128])[l];            // lane-varying
        const float4* ap = (const float4*)&tA[t * 128 + w * 16]; // warp-broadcast
        float4 aa[4];
        aa[0] = ap[0]; aa[1] = ap[1]; aa[2] = ap[2]; aa[3] = ap[3];
        const float* av = (const float*)aa;
        #pragma unroll
        for (int i = 0; i < 16; i++) {
            float a = av[i];
            acc[4*i+0] += a * bv.x;
            acc[4*i+1] += a * bv.y;
            acc[4*i+2] += a * bv.z;
            acc[4*i+3] += a * bv.w;
        }
    }

    // ---- epilogue: coalesced partial writes (code j = w*2048 + i*128 + l*4 + k)
    float4* dst = (float4*)(g_part + (size_t)blockIdx.x * KSIZE + w * 2048);
    #pragma unroll
    for (int i = 0; i < 16; i++)
        dst[i * 32 + l] = make_float4(acc[4*i], acc[4*i+1], acc[4*i+2], acc[4*i+3]);

    // ---- block scalar reductions
    #pragma unroll
    for (int off = 16; off; off >>= 1) hloc += __shfl_xor_sync(0xffffffffu, hloc, off);
    if (l == 0) { sred[w] = commit_acc; sred[8 + w] = hloc; }
    __syncthreads();
    if (tid == 0) {
        float c = 0.f, h = 0.f;
        #pragma unroll
        for (int i = 0; i < 8; i++) { c += sred[i]; h += sred[8 + i]; }
        g_sc[blockIdx.x] = c;
        g_se[blockIdx.x] = h;
    }
}

// ---------------------------------------------------------------- K3: reduce partials -> aux
// grid = 512 blocks x 256 threads. Block bx owns codes [bx*32, bx*32+32).
// Thread: code = bx*32 + (tid&31), chunk = tid>>5 (0..7) sums 32 partials
// (fully unrolled, 8 accumulators). 131K threads for deep DRAM demand.
__global__ __launch_bounds__(256) void k3(float* __restrict__ aux_out, float inv_ntok) {
    int tid = threadIdx.x;
    int code = blockIdx.x * 32 + (tid & 31);
    int chunk = tid >> 5;                         // 0..7
    const float* p = g_part + (size_t)chunk * 32 * KSIZE + code;

    float a0=0.f,a1=0.f,a2=0.f,a3=0.f,a4=0.f,a5=0.f,a6=0.f,a7=0.f;
    #pragma unroll
    for (int b = 0; b < 32; b += 8) {
        a0 += p[(size_t)(b    ) * KSIZE];
        a1 += p[(size_t)(b + 1) * KSIZE];
        a2 += p[(size_t)(b + 2) * KSIZE];
        a3 += p[(size_t)(b + 3) * KSIZE];
        a4 += p[(size_t)(b + 4) * KSIZE];
        a5 += p[(size_t)(b + 5) * KSIZE];
        a6 += p[(size_t)(b + 6) * KSIZE];
        a7 += p[(size_t)(b + 7) * KSIZE];
    }
    float v = ((a0 + a1) + (a2 + a3)) + ((a4 + a5) + (a6 + a7));

    __shared__ float sp[8][32];
    sp[chunk][tid & 31] = v;
    __syncthreads();

    if (tid < 32) {
        float a = ((sp[0][tid] + sp[1][tid]) + (sp[2][tid] + sp[3][tid]))
                + ((sp[4][tid] + sp[5][tid]) + (sp[6][tid] + sp[7][tid]));
        a *= inv_ntok;
        float s = -a * __logf(fmaxf(a, 1e-20f));
        #pragma unroll
        for (int off = 16; off; off >>= 1) s += __shfl_xor_sync(0xffffffffu, s, off);
        if (tid == 0) g_hc[blockIdx.x] = s;
    }

    // last-block-done finisher
    __threadfence();
    __shared__ int lastflag;
    if (tid == 0) lastflag = (atomicAdd(&g_done, 1) == R3BLK - 1);
    __syncthreads();
    if (lastflag) {
        float hc = g_hc[tid] + g_hc[tid + 256];   // R3BLK == 512 entries
        float sc = g_sc[tid];                     // NBLK == 256 entries
        float se = g_se[tid];
        #pragma unroll
        for (int off = 16; off; off >>= 1) {
            hc += __shfl_xor_sync(0xffffffffu, hc, off);
            sc += __shfl_xor_sync(0xffffffffu, sc, off);
            se += __shfl_xor_sync(0xffffffffu, se, off);
        }
        __shared__ float sr[3][8];
        int w = tid >> 5;
        if ((tid & 31) == 0) { sr[0][w] = hc; sr[1][w] = sc; sr[2][w] = se; }
        __syncthreads();
        if (tid == 0) {
            float Hc = 0.f, C = 0.f, Hs = 0.f;
            #pragma unroll
            for (int i = 0; i < 8; i++) { Hc += sr[0][i]; C += sr[1][i]; Hs += sr[2][i]; }
            float per_sample = Hs * inv_ntok;
            float commit = C * inv_ntok * (1.f / (float)CDIM);
            *aux_out = 0.1f * (per_sample - Hc) + 0.25f * commit;
            g_done = 0;                       // reset for next launch/replay
        }
    }
}

// ----------------------------------------------------------------
extern "C" void kernel_launch(void* const* d_in, const int* in_sizes, int n_in,
                              void* d_out, int out_size) {
    const float* x     = (const float*)d_in[0];
    const float* w_in  = (const float*)d_in[1];
    const float* b_in  = (const float*)d_in[2];
    const float* w_out = (const float*)d_in[3];
    const float* b_out = (const float*)d_in[4];

    int ntok = in_sizes[0] / DIM;               // 8192
    float* out     = (float*)d_out;
    float* idx_out = out + (size_t)ntok * DIM;
    float* aux_out = idx_out + ntok;

    float inv_ntok = 1.f / (float)ntok;

    kF<<<ntok / 32, 256>>>(x, w_in, b_in, w_out, b_out, out, idx_out);
    k3<<<R3BLK, 256>>>(aux_out, inv_ntok);
}

// round 11
// speedup vs baseline: 3.7791x; 1.0063x over previous
#include <cuda_runtime.h>
#include <math.h>

#define DIM     512
#define CDIM    14
#define KSIZE   16384
#define NBLK    256      // 8192 tokens / 32 per block
#define WOPITCH 520      // padded s_wout row pitch
#define R3BLK   512      // k3 grid

// scratch — static device globals (no allocation allowed)
__device__ float g_part[NBLK * KSIZE];   // per-block partial prob sums (16MB)
__device__ float g_sc[NBLK];             // per-block commit partial
__device__ float g_se[NBLK];             // per-block sample-entropy partial
__device__ float g_hc[R3BLK];            // per-k3-block codebook-entropy partial
__device__ int   g_done;                 // last-block-done counter (self-resetting)

#define PACK2(d, x, y)   asm("mov.b64 %0, {%1, %2};" : "=l"(d) : "f"(x), "f"(y))
#define UNPACK2(x, y, d) asm("mov.b64 {%0, %1}, %2;" : "=f"(x), "=f"(y) : "l"(d))
#define FMA2(acc, a, b)  asm("fma.rn.f32x2 %0, %1, %2, %0;" : "+l"(acc) : "l"(a), "l"(b))

// ---------------------------------------------------------------- fused kernel
// grid = 256 blocks x 256 threads; block owns 32 tokens (4 per warp).
__global__ __launch_bounds__(256, 2) void kF(
    const float* __restrict__ x,
    const float* __restrict__ w_in,   // [14][512]
    const float* __restrict__ b_in,   // [14]
    const float* __restrict__ w_out,  // [512][14]
    const float* __restrict__ b_out,  // [512]
    float* __restrict__ out,
    float* __restrict__ idx_out)
{
    // blob: stage A = s_wout (7280 used); stage C = tA[32][128] | tB[32][128]
    __shared__ __align__(16) float blob[8192];
    __shared__ float s_bin[16];
    __shared__ float sQ[32 * 16];              // p, then sigmoid(p) in place
    __shared__ float sred[16];

    float* s_wout = blob;
    float* tA = blob;
    float* tB = blob + 4096;

    int tid = threadIdx.x;
    for (int i = tid; i < CDIM * DIM; i += 256) {
        int d = i / CDIM, c = i % CDIM;
        s_wout[c * WOPITCH + d] = w_out[i];
    }
    if (tid < CDIM) s_bin[tid] = b_in[tid];
    __syncthreads();

    int w = tid >> 5, l = tid & 31;
    const float4* win4  = (const float4*)w_in;
    const float4* wout4 = (const float4*)s_wout;   // row stride 130 float4
    const float4* bout4 = (const float4*)b_out;

    int tok0   = w * 4;
    int token0 = blockIdx.x * 32 + tok0;

    // ---- stage A part 1: projection, 4 tokens jointly, k-outer
    float s0[CDIM], s1[CDIM], s2[CDIM], s3[CDIM];
    #pragma unroll
    for (int c = 0; c < CDIM; c++) { s0[c]=0.f; s1[c]=0.f; s2[c]=0.f; s3[c]=0.f; }

    #pragma unroll
    for (int k = 0; k < 4; k++) {
        float4 xv0 = ((const float4*)(x + (size_t)(token0    ) * DIM))[k * 32 + l];
        float4 xv1 = ((const float4*)(x + (size_t)(token0 + 1) * DIM))[k * 32 + l];
        float4 xv2 = ((const float4*)(x + (size_t)(token0 + 2) * DIM))[k * 32 + l];
        float4 xv3 = ((const float4*)(x + (size_t)(token0 + 3) * DIM))[k * 32 + l];
        #pragma unroll
        for (int c = 0; c < CDIM; c++) {
            float4 wv = win4[c * 128 + k * 32 + l];
            s0[c] += xv0.x*wv.x + xv0.y*wv.y + xv0.z*wv.z + xv0.w*wv.w;
            s1[c] += xv1.x*wv.x + xv1.y*wv.y + xv1.z*wv.z + xv1.w*wv.w;
            s2[c] += xv2.x*wv.x + xv2.y*wv.y + xv2.z*wv.z + xv2.w*wv.w;
            s3[c] += xv3.x*wv.x + xv3.y*wv.y + xv3.z*wv.z + xv3.w*wv.w;
        }
    }

    // fold reduction: lane group g = l>>3 ends owning token g.
    float pv[CDIM];
    #pragma unroll
    for (int c = 0; c < CDIM; c++) {
        float t0 = s0[c], t1 = s1[c], t2 = s2[c], t3 = s3[c];
        t0 += __shfl_xor_sync(0xffffffffu, t0, 16);
        t1 += __shfl_xor_sync(0xffffffffu, t1, 16);
        t2 += __shfl_xor_sync(0xffffffffu, t2, 16);
        t3 += __shfl_xor_sync(0xffffffffu, t3, 16);
        float a = (l < 16) ? t0 : t2;
        float b = (l < 16) ? t1 : t3;
        a += __shfl_xor_sync(0xffffffffu, a, 8);
        b += __shfl_xor_sync(0xffffffffu, b, 8);
        float m = (l & 8) ? b : a;
        m += __shfl_xor_sync(0xffffffffu, m, 4);
        m += __shfl_xor_sync(0xffffffffu, m, 2);
        m += __shfl_xor_sync(0xffffffffu, m, 1);
        pv[c] = m + s_bin[c];
    }

    int g = l >> 3;
    unsigned idx = 0;
    float commit = 0.f;
    #pragma unroll
    for (int c = 0; c < CDIM; c++) {
        bool pos = pv[c] > 0.f;
        idx |= (pos ? 1u : 0u) << (13 - c);
        float sg = pos ? 1.f : -1.f;
        float d = pv[c] - sg;
        commit += d * d;
    }
    if ((l & 7) == 0) {
        idx_out[token0 + g] = (float)idx;
        #pragma unroll
        for (int c = 0; c < CDIM; c++) sQ[(tok0 + g) * 16 + c] = pv[c];
    }

    unsigned idxs[4];
    #pragma unroll
    for (int t = 0; t < 4; t++) idxs[t] = __shfl_sync(0xffffffffu, idx, t * 8);
    commit += __shfl_xor_sync(0xffffffffu, commit, 8);
    commit += __shfl_xor_sync(0xffffffffu, commit, 16);
    float commit_acc = commit;

    float sg[4][CDIM];
    #pragma unroll
    for (int t = 0; t < 4; t++)
        #pragma unroll
        for (int c = 0; c < CDIM; c++)
            sg[t][c] = ((idxs[t] >> (13 - c)) & 1) ? 1.f : -1.f;

    // ---- stage A part 2: project-out, 4 tokens jointly, k-outer
    #pragma unroll
    for (int k = 0; k < 4; k++) {
        float4 bb = bout4[k * 32 + l];
        float4 a[4];
        #pragma unroll
        for (int t = 0; t < 4; t++) a[t] = bb;
        #pragma unroll
        for (int c = 0; c < CDIM; c++) {
            float4 wv = wout4[c * 130 + k * 32 + l];
            #pragma unroll
            for (int t = 0; t < 4; t++) {
                a[t].x += sg[t][c] * wv.x; a[t].y += sg[t][c] * wv.y;
                a[t].z += sg[t][c] * wv.z; a[t].w += sg[t][c] * wv.w;
            }
        }
        #pragma unroll
        for (int t = 0; t < 4; t++)
            ((float4*)(out + (size_t)(token0 + t) * DIM))[k * 32 + l] = a[t];
    }
    __syncthreads();

    // ---- stage B: sigmoids (in place) + per-sample entropy partial
    float hloc = 0.f;
    for (int i = tid; i < 32 * CDIM; i += 256) {
        int tok = i / CDIM, c = i % CDIM;
        float p = sQ[tok * 16 + c];
        float q = 1.f / (1.f + __expf(-400.f * p));
        sQ[tok * 16 + c] = q;
        float qm = 1.f - q;
        hloc += -(q  * __logf(fmaxf(q,  1e-20f)) +
                  qm * __logf(fmaxf(qm, 1e-20f)));
    }
    __syncthreads();    // q ready; s_wout dead -> blob becomes tables

    // ---- stage C build: all 32 token tables, one pass
    #pragma unroll 1
    for (int t = 0; t < 32; t++) {
        const float4* q4 = (const float4*)&sQ[t * 16];
        if (tid < 128) {                       // A over c = 0..6 (bits 13..7)
            float4 qa = q4[0], qb = q4[1];
            float v = ((tid & 64) ? qa.x : 1.f - qa.x)
                    * ((tid & 32) ? qa.y : 1.f - qa.y)
                    * ((tid & 16) ? qa.z : 1.f - qa.z)
                    * ((tid &  8) ? qa.w : 1.f - qa.w)
                    * ((tid &  4) ? qb.x : 1.f - qb.x)
                    * ((tid &  2) ? qb.y : 1.f - qb.y)
                    * ((tid &  1) ? qb.z : 1.f - qb.z);
            tA[t * 128 + tid] = v;
        } else {                               // B over c = 7..13 (bits 6..0)
            int lo = tid - 128;
            float4 qb = q4[1], qc = q4[2], qd = q4[3];
            float v = ((lo & 64) ? qb.w : 1.f - qb.w)
                    * ((lo & 32) ? qc.x : 1.f - qc.x)
                    * ((lo & 16) ? qc.y : 1.f - qc.y)
                    * ((lo &  8) ? qc.z : 1.f - qc.z)
                    * ((lo &  4) ? qc.w : 1.f - qc.w)
                    * ((lo &  2) ? qd.x : 1.f - qd.x)
                    * ((lo &  1) ? qd.y : 1.f - qd.y);
            tB[t * 128 + lo] = v;
        }
    }
    __syncthreads();

    // ---- stage C consume: barrier-free packed-FFMA2 stream
    // acc2[i2*4+k] holds codes (hi = w*16+2*i2, lo = l*4+k) in lane0 and
    // (hi+1, same lo) in lane1 of the f32x2.
    unsigned long long acc2[32];
    #pragma unroll
    for (int i = 0; i < 32; i++) acc2[i] = 0ull;   // (0.f, 0.f)

    #pragma unroll 2
    for (int t = 0; t < 32; t++) {
        float4 bv = ((const float4*)&tB[t * 128])[l];         // lane-varying
        unsigned long long bd0, bd1, bd2, bd3;
        PACK2(bd0, bv.x, bv.x); PACK2(bd1, bv.y, bv.y);
        PACK2(bd2, bv.z, bv.z); PACK2(bd3, bv.w, bv.w);
        const float4* ap = (const float4*)&tA[t * 128 + w * 16]; // broadcast
        #pragma unroll
        for (int i2g = 0; i2g < 4; i2g++) {
            float4 aa = ap[i2g];
            unsigned long long ad0, ad1;
            PACK2(ad0, aa.x, aa.y);
            PACK2(ad1, aa.z, aa.w);
            int base = i2g * 8;
            FMA2(acc2[base + 0], ad0, bd0);
            FMA2(acc2[base + 1], ad0, bd1);
            FMA2(acc2[base + 2], ad0, bd2);
            FMA2(acc2[base + 3], ad0, bd3);
            FMA2(acc2[base + 4], ad1, bd0);
            FMA2(acc2[base + 5], ad1, bd1);
            FMA2(acc2[base + 6], ad1, bd2);
            FMA2(acc2[base + 7], ad1, bd3);
        }
    }

    // ---- epilogue: unpack + coalesced writes (code j = w*2048 + i*128 + l*4 + k)
    float4* dst = (float4*)(g_part + (size_t)blockIdx.x * KSIZE + w * 2048);
    #pragma unroll
    for (int i2 = 0; i2 < 8; i2++) {
        float lo0, hi0, lo1, hi1, lo2, hi2, lo3, hi3;
        UNPACK2(lo0, hi0, acc2[i2 * 4 + 0]);
        UNPACK2(lo1, hi1, acc2[i2 * 4 + 1]);
        UNPACK2(lo2, hi2, acc2[i2 * 4 + 2]);
        UNPACK2(lo3, hi3, acc2[i2 * 4 + 3]);
        dst[(2 * i2    ) * 32 + l] = make_float4(lo0, lo1, lo2, lo3);
        dst[(2 * i2 + 1) * 32 + l] = make_float4(hi0, hi1, hi2, hi3);
    }

    // ---- block scalar reductions
    #pragma unroll
    for (int off = 16; off; off >>= 1) hloc += __shfl_xor_sync(0xffffffffu, hloc, off);
    if (l == 0) { sred[w] = commit_acc; sred[8 + w] = hloc; }
    __syncthreads();
    if (tid == 0) {
        float c = 0.f, h = 0.f;
        #pragma unroll
        for (int i = 0; i < 8; i++) { c += sred[i]; h += sred[8 + i]; }
        g_sc[blockIdx.x] = c;
        g_se[blockIdx.x] = h;
    }
}

// ---------------------------------------------------------------- K3: reduce partials -> aux
// grid = 512 blocks x 256 threads. Block bx owns 32 codes = 8 float4 quads.
// Thread: quad = bx*8 + (tid&7), chunk = tid>>3 (0..31), sums 8 partials via
// LDG.128 (16B per outstanding load -> 16MB in flight chip-wide).
__global__ __launch_bounds__(256) void k3(float* __restrict__ aux_out, float inv_ntok) {
    int tid = threadIdx.x;
    int quad  = blockIdx.x * 8 + (tid & 7);       // float4 index (4 codes)
    int chunk = tid >> 3;                         // 0..31, 8 partials each
    const float4* p4 = (const float4*)g_part;     // [partial*4096 + quad]
    size_t base = (size_t)chunk * 8 * 4096 + quad;

    float4 v0 = p4[base          ];
    float4 v1 = p4[base + 1*4096 ];
    float4 v2 = p4[base + 2*4096 ];
    float4 v3 = p4[base + 3*4096 ];
    float4 v4 = p4[base + 4*4096 ];
    float4 v5 = p4[base + 5*4096 ];
    float4 v6 = p4[base + 6*4096 ];
    float4 v7 = p4[base + 7*4096 ];
    float4 v;
    v.x = ((v0.x+v1.x)+(v2.x+v3.x)) + ((v4.x+v5.x)+(v6.x+v7.x));
    v.y = ((v0.y+v1.y)+(v2.y+v3.y)) + ((v4.y+v5.y)+(v6.y+v7.y));
    v.z = ((v0.z+v1.z)+(v2.z+v3.z)) + ((v4.z+v5.z)+(v6.z+v7.z));
    v.w = ((v0.w+v1.w)+(v2.w+v3.w)) + ((v4.w+v5.w)+(v6.w+v7.w));

    __shared__ float sp[32][32];                  // [chunk][local code]
    *((float4*)&sp[chunk][(tid & 7) * 4]) = v;
    __syncthreads();

    if (tid < 32) {
        float a = 0.f;
        #pragma unroll
        for (int c = 0; c < 32; c += 4)
            a += (sp[c][tid] + sp[c+1][tid]) + (sp[c+2][tid] + sp[c+3][tid]);
        a *= inv_ntok;
        float s = -a * __logf(fmaxf(a, 1e-20f));
        #pragma unroll
        for (int off = 16; off; off >>= 1) s += __shfl_xor_sync(0xffffffffu, s, off);
        if (tid == 0) g_hc[blockIdx.x] = s;
    }

    // last-block-done finisher
    __threadfence();
    __shared__ int lastflag;
    if (tid == 0) lastflag = (atomicAdd(&g_done, 1) == R3BLK - 1);
    __syncthreads();
    if (lastflag) {
        float hc = g_hc[tid] + g_hc[tid + 256];   // R3BLK == 512 entries
        float sc = g_sc[tid];                     // NBLK == 256 entries
        float se = g_se[tid];
        #pragma unroll
        for (int off = 16; off; off >>= 1) {
            hc += __shfl_xor_sync(0xffffffffu, hc, off);
            sc += __shfl_xor_sync(0xffffffffu, sc, off);
            se += __shfl_xor_sync(0xffffffffu, se, off);
        }
        __shared__ float sr[3][8];
        int w = tid >> 5;
        if ((tid & 31) == 0) { sr[0][w] = hc; sr[1][w] = sc; sr[2][w] = se; }
        __syncthreads();
        if (tid == 0) {
            float Hc = 0.f, C = 0.f, Hs = 0.f;
            #pragma unroll
            for (int i = 0; i < 8; i++) { Hc += sr[0][i]; C += sr[1][i]; Hs += sr[2][i]; }
            float per_sample = Hs * inv_ntok;
            float commit = C * inv_ntok * (1.f / (float)CDIM);
            *aux_out = 0.1f * (per_sample - Hc) + 0.25f * commit;
            g_done = 0;                       // reset for next launch/replay
        }
    }
}

// ----------------------------------------------------------------
extern "C" void kernel_launch(void* const* d_in, const int* in_sizes, int n_in,
                              void* d_out, int out_size) {
    const float* x     = (const float*)d_in[0];
    const float* w_in  = (const float*)d_in[1];
    const float* b_in  = (const float*)d_in[2];
    const float* w_out = (const float*)d_in[3];
    const float* b_out = (const float*)d_in[4];

    int ntok = in_sizes[0] / DIM;               // 8192
    float* out     = (float*)d_out;
    float* idx_out = out + (size_t)ntok * DIM;
    float* aux_out = idx_out + ntok;

    float inv_ntok = 1.f / (float)ntok;

    kF<<<ntok / 32, 256>>>(x, w_in, b_in, w_out, b_out, out, idx_out);
    k3<<<R3BLK, 256>>>(aux_out, inv_ntok);
}